// round 1
// baseline (speedup 1.0000x reference)
#include <cuda_runtime.h>

// Problem constants
#define BB 8
#define TT 2048
#define EE 1024
#define HS 64

// Scratch for q, k, v projections: [B, T, HS] fp32 each (4 MB each)
__device__ float g_q[BB * TT * HS];
__device__ float g_k[BB * TT * HS];
__device__ float g_v[BB * TT * HS];

// ---------------------------------------------------------------------------
// Kernel 1: QKV projection.  out[m][h] = sum_e X[m][e] * W[h][e] + b[h]
// M = B*T = 16384, N = HS = 64, K = E = 1024.
// Grid: (M/128, 3)  — blockIdx.y selects q/k/v.  256 threads.
// ---------------------------------------------------------------------------
#define GBM 128
#define GBN 64
#define GBK 16

__global__ __launch_bounds__(256) void qkv_kernel(
    const float* __restrict__ X,
    const float* __restrict__ Wq, const float* __restrict__ bq,
    const float* __restrict__ Wk, const float* __restrict__ bk,
    const float* __restrict__ Wv, const float* __restrict__ bv)
{
    const float* W;
    const float* bias;
    float* out;
    if (blockIdx.y == 0)      { W = Wq; bias = bq; out = g_q; }
    else if (blockIdx.y == 1) { W = Wk; bias = bk; out = g_k; }
    else                      { W = Wv; bias = bv; out = g_v; }

    __shared__ float As[GBK][GBM];   // X tile, transposed: As[k][m]
    __shared__ float Bs[GBK][GBN];   // W tile, transposed: Bs[k][n]

    const int tid = threadIdx.x;          // 0..255
    const int tx = tid & 15;              // 0..15 -> output col group (n)
    const int ty = tid >> 4;              // 0..15 -> output row group (m)
    const int m0 = blockIdx.x * GBM;

    float acc[8][4];
    #pragma unroll
    for (int i = 0; i < 8; i++)
        #pragma unroll
        for (int j = 0; j < 4; j++) acc[i][j] = 0.0f;

    for (int k0 = 0; k0 < EE; k0 += GBK) {
        // Load X tile: 128 rows x 16 cols = 512 float4; 2 per thread
        #pragma unroll
        for (int p = 0; p < 2; p++) {
            int t = p * 256 + tid;
            int r = t >> 2;              // 0..127
            int c4 = (t & 3) * 4;        // 0,4,8,12
            float4 v = *(const float4*)&X[(size_t)(m0 + r) * EE + k0 + c4];
            As[c4 + 0][r] = v.x;
            As[c4 + 1][r] = v.y;
            As[c4 + 2][r] = v.z;
            As[c4 + 3][r] = v.w;
        }
        // Load W tile: 64 rows x 16 cols = 256 float4; 1 per thread
        {
            int r = tid >> 2;            // 0..63
            int c4 = (tid & 3) * 4;
            float4 v = *(const float4*)&W[(size_t)r * EE + k0 + c4];
            Bs[c4 + 0][r] = v.x;
            Bs[c4 + 1][r] = v.y;
            Bs[c4 + 2][r] = v.z;
            Bs[c4 + 3][r] = v.w;
        }
        __syncthreads();

        #pragma unroll
        for (int kk = 0; kk < GBK; kk++) {
            float a[8], b[4];
            *(float4*)&a[0] = *(float4*)&As[kk][ty * 8];
            *(float4*)&a[4] = *(float4*)&As[kk][ty * 8 + 4];
            *(float4*)&b[0] = *(float4*)&Bs[kk][tx * 4];
            #pragma unroll
            for (int i = 0; i < 8; i++)
                #pragma unroll
                for (int j = 0; j < 4; j++)
                    acc[i][j] += a[i] * b[j];
        }
        __syncthreads();
    }

    float4 bb = *(const float4*)&bias[tx * 4];
    #pragma unroll
    for (int i = 0; i < 8; i++) {
        float4 o;
        o.x = acc[i][0] + bb.x;
        o.y = acc[i][1] + bb.y;
        o.z = acc[i][2] + bb.z;
        o.w = acc[i][3] + bb.w;
        *(float4*)&out[(size_t)(m0 + ty * 8 + i) * HS + tx * 4] = o;
    }
}

// ---------------------------------------------------------------------------
// Kernel 2: causal flash attention, fp32.
// One block per (64-query tile, batch).  256 threads (16x16).
// smem: Qt (hs-major) 16KB + Kt/P shared buffer 16KB + V 16KB = 48KB exactly.
// Each thread owns a 4x4 tile of S/P (rows ty*4.., cols tx*4..) and a 4x4
// tile of O (rows ty*4.., hs cols tx*4..).  Row m/l stats live in registers,
// replicated across the 16 tx-threads of each row group via shfl_xor.
// ---------------------------------------------------------------------------
__global__ __launch_bounds__(256) void attn_kernel(float* __restrict__ out)
{
    const int qt = (TT / 64 - 1) - blockIdx.x;   // big tiles first
    const int b  = blockIdx.y;
    const int q0 = qt * 64;

    __shared__ float Qt[64][64];    // [hs][q]   (transposed, pre-scaled)
    __shared__ float KtP[64][64];   // K as [hs][key]; reused as P [q][key]
    __shared__ float Vs[64][64];    // [key][hs]

    const int tid = threadIdx.x;
    const int tx = tid & 15;
    const int ty = tid >> 4;

    // Load Q tile transposed, pre-scaled by 1/sqrt(HS) = 0.125
    {
        const float* qbase = g_q + ((size_t)b * TT + q0) * HS;
        #pragma unroll
        for (int p = 0; p < 4; p++) {
            int t = p * 256 + tid;     // 0..1023
            int r = t >> 4;            // 0..63  (query row)
            int c4 = (t & 15) * 4;     // 0..60  (hs col)
            float4 v = *(const float4*)&qbase[(size_t)r * HS + c4];
            Qt[c4 + 0][r] = v.x * 0.125f;
            Qt[c4 + 1][r] = v.y * 0.125f;
            Qt[c4 + 2][r] = v.z * 0.125f;
            Qt[c4 + 3][r] = v.w * 0.125f;
        }
    }

    float O[4][4];
    #pragma unroll
    for (int i = 0; i < 4; i++)
        #pragma unroll
        for (int j = 0; j < 4; j++) O[i][j] = 0.0f;
    float mrow[4] = {-1e30f, -1e30f, -1e30f, -1e30f};
    float lrow[4] = {0.0f, 0.0f, 0.0f, 0.0f};

    for (int kb = 0; kb <= qt; kb++) {
        __syncthreads();   // previous iteration's AV reads of KtP/Vs done

        // Load K tile (transposed -> KtP) and V tile (row-major -> Vs)
        {
            const float* kbase = g_k + ((size_t)b * TT + kb * 64) * HS;
            const float* vbase = g_v + ((size_t)b * TT + kb * 64) * HS;
            #pragma unroll
            for (int p = 0; p < 4; p++) {
                int t = p * 256 + tid;
                int r = t >> 4;
                int c4 = (t & 15) * 4;
                float4 kv = *(const float4*)&kbase[(size_t)r * HS + c4];
                KtP[c4 + 0][r] = kv.x;
                KtP[c4 + 1][r] = kv.y;
                KtP[c4 + 2][r] = kv.z;
                KtP[c4 + 3][r] = kv.w;
                *(float4*)&Vs[r][c4] = *(const float4*)&vbase[(size_t)r * HS + c4];
            }
        }
        __syncthreads();

        // S = Q K^T  (already scaled) — 4x4 per-thread tile
        float s[4][4];
        #pragma unroll
        for (int i = 0; i < 4; i++)
            #pragma unroll
            for (int j = 0; j < 4; j++) s[i][j] = 0.0f;

        #pragma unroll 16
        for (int k = 0; k < 64; k++) {
            float4 qa = *(float4*)&Qt[k][ty * 4];
            float4 kbv = *(float4*)&KtP[k][tx * 4];
            float a[4] = {qa.x, qa.y, qa.z, qa.w};
            float bv[4] = {kbv.x, kbv.y, kbv.z, kbv.w};
            #pragma unroll
            for (int i = 0; i < 4; i++)
                #pragma unroll
                for (int j = 0; j < 4; j++)
                    s[i][j] += a[i] * bv[j];
        }
        __syncthreads();   // all reads of KtP (as K) done before P overwrite

        // Causal mask: only the diagonal tile needs it (q0 == k0 there)
        if (kb == qt) {
            #pragma unroll
            for (int i = 0; i < 4; i++)
                #pragma unroll
                for (int j = 0; j < 4; j++)
                    if (tx * 4 + j > ty * 4 + i) s[i][j] = -1e30f;
        }

        // Online softmax per row group; write P into KtP buffer
        #pragma unroll
        for (int i = 0; i < 4; i++) {
            float mx = fmaxf(fmaxf(s[i][0], s[i][1]), fmaxf(s[i][2], s[i][3]));
            #pragma unroll
            for (int o = 8; o >= 1; o >>= 1)
                mx = fmaxf(mx, __shfl_xor_sync(0xffffffffu, mx, o));
            float mnew = fmaxf(mrow[i], mx);
            float alpha = expf(mrow[i] - mnew);
            float sum = 0.0f;
            #pragma unroll
            for (int j = 0; j < 4; j++) {
                s[i][j] = expf(s[i][j] - mnew);
                sum += s[i][j];
            }
            #pragma unroll
            for (int o = 8; o >= 1; o >>= 1)
                sum += __shfl_xor_sync(0xffffffffu, sum, o);
            lrow[i] = lrow[i] * alpha + sum;
            mrow[i] = mnew;
            #pragma unroll
            for (int j = 0; j < 4; j++) O[i][j] *= alpha;
            float4 pw = make_float4(s[i][0], s[i][1], s[i][2], s[i][3]);
            *(float4*)&KtP[ty * 4 + i][tx * 4] = pw;
        }
        __syncthreads();

        // O += P @ V   (P: [q][key] in KtP, V: [key][hs])
        #pragma unroll
        for (int jj = 0; jj < 16; jj++) {
            float4 pv[4];
            #pragma unroll
            for (int i = 0; i < 4; i++)
                pv[i] = *(float4*)&KtP[ty * 4 + i][jj * 4];
            float4 vv[4];
            #pragma unroll
            for (int j2 = 0; j2 < 4; j2++)
                vv[j2] = *(float4*)&Vs[jj * 4 + j2][tx * 4];
            #pragma unroll
            for (int i = 0; i < 4; i++) {
                float p0 = pv[i].x, p1 = pv[i].y, p2 = pv[i].z, p3 = pv[i].w;
                O[i][0] += p0 * vv[0].x + p1 * vv[1].x + p2 * vv[2].x + p3 * vv[3].x;
                O[i][1] += p0 * vv[0].y + p1 * vv[1].y + p2 * vv[2].y + p3 * vv[3].y;
                O[i][2] += p0 * vv[0].z + p1 * vv[1].z + p2 * vv[2].z + p3 * vv[3].z;
                O[i][3] += p0 * vv[0].w + p1 * vv[1].w + p2 * vv[2].w + p3 * vv[3].w;
            }
        }
    }

    // Epilogue: O / l, write out
    float* obase = out + ((size_t)b * TT + q0) * HS;
    #pragma unroll
    for (int i = 0; i < 4; i++) {
        float inv = 1.0f / lrow[i];
        float4 o;
        o.x = O[i][0] * inv;
        o.y = O[i][1] * inv;
        o.z = O[i][2] * inv;
        o.w = O[i][3] * inv;
        *(float4*)&obase[(size_t)(ty * 4 + i) * HS + tx * 4] = o;
    }
}

// ---------------------------------------------------------------------------
extern "C" void kernel_launch(void* const* d_in, const int* in_sizes, int n_in,
                              void* d_out, int out_size)
{
    const float* X  = (const float*)d_in[0];
    const float* Wq = (const float*)d_in[1];
    const float* bq = (const float*)d_in[2];
    const float* Wk = (const float*)d_in[3];
    const float* bk = (const float*)d_in[4];
    const float* Wv = (const float*)d_in[5];
    const float* bv = (const float*)d_in[6];
    float* out = (float*)d_out;

    dim3 g1(BB * TT / GBM, 3);           // (128, 3)
    qkv_kernel<<<g1, 256>>>(X, Wq, bq, Wk, bk, Wv, bv);

    dim3 g2(TT / 64, BB);                // (32, 8)
    attn_kernel<<<g2, 256>>>(out);
}

// round 3
// speedup vs baseline: 1.4933x; 1.4933x over previous
#include <cuda_runtime.h>
#include <cuda_bf16.h>
#include <cstdint>

#define BB 8
#define TT 2048
#define EE 1024
#define HS 64
#define NTOT 192   // q(64) | k(64) | v(64)

// Scratch
__device__ float g_q[BB * TT * HS];
__device__ float g_k[BB * TT * HS];
__device__ float g_v[BB * TT * HS];
__device__ __nv_bfloat16 g_Wh[NTOT * EE];
__device__ __nv_bfloat16 g_Wl[NTOT * EE];

// ---------------------------------------------------------------------------
// Helpers
// ---------------------------------------------------------------------------
__device__ __forceinline__ uint32_t smem_u32(const void* p) {
    uint32_t a;
    asm("{ .reg .u64 t; cvta.to.shared.u64 t, %1; cvt.u32.u64 %0, t; }"
        : "=r"(a) : "l"(p));
    return a;
}

__device__ __forceinline__ void cp16(uint32_t dst, const void* src) {
    asm volatile("cp.async.cg.shared.global [%0], [%1], 16;"
                 :: "r"(dst), "l"(src));
}

__device__ __forceinline__ void mma16816(float* c, const uint32_t* a,
                                         const uint32_t* b) {
    asm volatile(
        "mma.sync.aligned.m16n8k16.row.col.f32.bf16.bf16.f32 "
        "{%0,%1,%2,%3}, {%4,%5,%6,%7}, {%8,%9}, {%0,%1,%2,%3};"
        : "+f"(c[0]), "+f"(c[1]), "+f"(c[2]), "+f"(c[3])
        : "r"(a[0]), "r"(a[1]), "r"(a[2]), "r"(a[3]), "r"(b[0]), "r"(b[1]));
}

// hi/lo bf16 split of a float4
__device__ __forceinline__ void split4(float4 v, uint2& hi, uint2& lo) {
    __nv_bfloat162 h0 = __floats2bfloat162_rn(v.x, v.y);
    __nv_bfloat162 h1 = __floats2bfloat162_rn(v.z, v.w);
    float2 f0 = __bfloat1622float2(h0);
    float2 f1 = __bfloat1622float2(h1);
    __nv_bfloat162 l0 = __floats2bfloat162_rn(v.x - f0.x, v.y - f0.y);
    __nv_bfloat162 l1 = __floats2bfloat162_rn(v.z - f1.x, v.w - f1.y);
    hi.x = *(uint32_t*)&h0; hi.y = *(uint32_t*)&h1;
    lo.x = *(uint32_t*)&l0; lo.y = *(uint32_t*)&l1;
}

// ---------------------------------------------------------------------------
// Kernel 0: convert concat(Wq,Wk,Wv) fp32 -> bf16 hi/lo, row-major [192][1024]
// ---------------------------------------------------------------------------
__global__ __launch_bounds__(256) void w_convert_kernel(
    const float* __restrict__ Wq, const float* __restrict__ Wk,
    const float* __restrict__ Wv)
{
    int idx = blockIdx.x * 256 + threadIdx.x;     // 49152 float4s total
    int e4 = idx * 4;
    int n = e4 >> 10;
    int c = e4 & 1023;
    const float* src = (n < 64) ? &Wq[n * 1024 + c]
                     : (n < 128) ? &Wk[(n - 64) * 1024 + c]
                     : &Wv[(n - 128) * 1024 + c];
    float4 v = *(const float4*)src;
    uint2 hi, lo;
    split4(v, hi, lo);
    *(uint2*)&g_Wh[e4] = hi;
    *(uint2*)&g_Wl[e4] = lo;
}

// ---------------------------------------------------------------------------
// Kernel 1: QKV projection via mma.sync bf16 (3-term hi/lo split).
// D[128,192] per CTA = X[128,1024] * W^T.  8 warps: 2 (M) x 4 (N).
// smem stage: A 128 rows x 128B (hi units 0-3, lo units 4-7, XOR-swizzled
// by row&7) + B 192 rows x 128B same layout.  Double buffered.
// ---------------------------------------------------------------------------
#define STAGE 40960
#define BOFF  16384
#define SMEM_QKV (2 * STAGE)

__global__ void __launch_bounds__(256) qkv_mma_kernel(
    const float* __restrict__ X,
    const float* __restrict__ bq, const float* __restrict__ bk,
    const float* __restrict__ bv)
{
    extern __shared__ __align__(128) char sm[];
    const uint32_t smb = smem_u32(sm);
    const int tid = threadIdx.x;
    const int lid = tid & 31;
    const int wid = tid >> 5;
    const int wm  = wid >> 2;        // 0..1  (64 M rows each)
    const int wn  = wid & 3;         // 0..3  (48 N cols each)
    const int lg  = lid >> 2;        // 0..7
    const int lt  = lid & 3;         // 0..3
    const int m0  = blockIdx.x * 128;

    float acc[4][6][4];
    #pragma unroll
    for (int t = 0; t < 4; t++)
        #pragma unroll
        for (int u = 0; u < 6; u++)
            #pragma unroll
            for (int r = 0; r < 4; r++) acc[t][u][r] = 0.0f;

    float4 xr[4];

    // ---- prologue: chunk 0
    {
        const int k0 = 0;
        #pragma unroll
        for (int p = 0; p < 4; p++) {
            int i = p * 256 + tid;
            int row = i >> 3, c4 = (i & 7) * 4;
            xr[p] = *(const float4*)&X[(size_t)(m0 + row) * EE + k0 + c4];
        }
        #pragma unroll
        for (int j = 0; j < 6; j++) {
            int idx = j * 256 + tid;          // 0..1535
            int n = idx >> 3, u = idx & 7;
            int kg = u & 3, wh = u >> 2;
            const __nv_bfloat16* s =
                (wh ? g_Wl : g_Wh) + n * EE + k0 + kg * 8;
            cp16(smb + BOFF + n * 128 + ((u ^ (n & 7)) * 16), s);
        }
        asm volatile("cp.async.commit_group;");
        #pragma unroll
        for (int p = 0; p < 4; p++) {
            int i = p * 256 + tid;
            int row = i >> 3, c4 = (i & 7) * 4;
            int kg = c4 >> 3, bo = (c4 & 4) * 2;
            uint2 hi, lo;
            split4(xr[p], hi, lo);
            *(uint2*)(sm + row * 128 + ((kg ^ (row & 7)) * 16) + bo) = hi;
            *(uint2*)(sm + row * 128 + (((kg | 4) ^ (row & 7)) * 16) + bo) = lo;
        }
        asm volatile("cp.async.wait_group 0;");
        __syncthreads();
    }

    for (int c = 0; c < 32; c++) {
        const int cb = c & 1;
        const int nb = (c + 1) & 1;
        if (c < 31) {
            const int k0 = (c + 1) * 32;
            #pragma unroll
            for (int p = 0; p < 4; p++) {
                int i = p * 256 + tid;
                int row = i >> 3, c4 = (i & 7) * 4;
                xr[p] = *(const float4*)&X[(size_t)(m0 + row) * EE + k0 + c4];
            }
            #pragma unroll
            for (int j = 0; j < 6; j++) {
                int idx = j * 256 + tid;
                int n = idx >> 3, u = idx & 7;
                int kg = u & 3, wh = u >> 2;
                const __nv_bfloat16* s =
                    (wh ? g_Wl : g_Wh) + n * EE + k0 + kg * 8;
                cp16(smb + nb * STAGE + BOFF + n * 128 + ((u ^ (n & 7)) * 16), s);
            }
            asm volatile("cp.async.commit_group;");
        }

        // ---- compute chunk c from buffer cb (two k16 steps)
        const char* ab = sm + cb * STAGE;
        const char* bb = ab + BOFF;
        #pragma unroll
        for (int h = 0; h < 2; h++) {
            uint32_t afh[4][4], afl[4][4], bfh[6][2], bfl[6][2];
            #pragma unroll
            for (int t = 0; t < 4; t++) {
                int r  = wm * 64 + t * 16 + lg;
                int r8 = r + 8;
                int kg0 = 2 * h, kg1 = 2 * h + 1;
                afh[t][0] = *(const uint32_t*)(ab + r  * 128 + ((kg0 ^ (r  & 7)) * 16) + lt * 4);
                afh[t][1] = *(const uint32_t*)(ab + r8 * 128 + ((kg0 ^ (r8 & 7)) * 16) + lt * 4);
                afh[t][2] = *(const uint32_t*)(ab + r  * 128 + ((kg1 ^ (r  & 7)) * 16) + lt * 4);
                afh[t][3] = *(const uint32_t*)(ab + r8 * 128 + ((kg1 ^ (r8 & 7)) * 16) + lt * 4);
                afl[t][0] = *(const uint32_t*)(ab + r  * 128 + (((kg0 | 4) ^ (r  & 7)) * 16) + lt * 4);
                afl[t][1] = *(const uint32_t*)(ab + r8 * 128 + (((kg0 | 4) ^ (r8 & 7)) * 16) + lt * 4);
                afl[t][2] = *(const uint32_t*)(ab + r  * 128 + (((kg1 | 4) ^ (r  & 7)) * 16) + lt * 4);
                afl[t][3] = *(const uint32_t*)(ab + r8 * 128 + (((kg1 | 4) ^ (r8 & 7)) * 16) + lt * 4);
            }
            #pragma unroll
            for (int u = 0; u < 6; u++) {
                int n = wn * 48 + u * 8 + lg;
                int kg0 = 2 * h, kg1 = 2 * h + 1;
                bfh[u][0] = *(const uint32_t*)(bb + n * 128 + ((kg0 ^ (n & 7)) * 16) + lt * 4);
                bfh[u][1] = *(const uint32_t*)(bb + n * 128 + ((kg1 ^ (n & 7)) * 16) + lt * 4);
                bfl[u][0] = *(const uint32_t*)(bb + n * 128 + (((kg0 | 4) ^ (n & 7)) * 16) + lt * 4);
                bfl[u][1] = *(const uint32_t*)(bb + n * 128 + (((kg1 | 4) ^ (n & 7)) * 16) + lt * 4);
            }
            #pragma unroll
            for (int t = 0; t < 4; t++)
                #pragma unroll
                for (int u = 0; u < 6; u++)
                    mma16816(acc[t][u], afh[t], bfh[u]);
            #pragma unroll
            for (int t = 0; t < 4; t++)
                #pragma unroll
                for (int u = 0; u < 6; u++)
                    mma16816(acc[t][u], afh[t], bfl[u]);
            #pragma unroll
            for (int t = 0; t < 4; t++)
                #pragma unroll
                for (int u = 0; u < 6; u++)
                    mma16816(acc[t][u], afl[t], bfh[u]);
        }

        if (c < 31) {
            #pragma unroll
            for (int p = 0; p < 4; p++) {
                int i = p * 256 + tid;
                int row = i >> 3, c4 = (i & 7) * 4;
                int kg = c4 >> 3, bo = (c4 & 4) * 2;
                uint2 hi, lo;
                split4(xr[p], hi, lo);
                *(uint2*)(sm + nb * STAGE + row * 128 + ((kg ^ (row & 7)) * 16) + bo) = hi;
                *(uint2*)(sm + nb * STAGE + row * 128 + (((kg | 4) ^ (row & 7)) * 16) + bo) = lo;
            }
            asm volatile("cp.async.wait_group 0;");
        }
        __syncthreads();
    }

    // ---- epilogue: add bias, write fp32 to g_q/g_k/g_v
    #pragma unroll
    for (int t = 0; t < 4; t++) {
        int r = m0 + wm * 64 + t * 16 + lg;
        #pragma unroll
        for (int u = 0; u < 6; u++) {
            int n = wn * 48 + u * 8 + lt * 2;
            float* dst;
            int col;
            const float* barr;
            if (n < 64)       { dst = g_q; col = n;       barr = bq; }
            else if (n < 128) { dst = g_k; col = n - 64;  barr = bk; }
            else              { dst = g_v; col = n - 128; barr = bv; }
            float b0 = __ldg(&barr[col]);
            float b1 = __ldg(&barr[col + 1]);
            float2 o0 = make_float2(acc[t][u][0] + b0, acc[t][u][1] + b1);
            float2 o1 = make_float2(acc[t][u][2] + b0, acc[t][u][3] + b1);
            *(float2*)&dst[(size_t)r * HS + col] = o0;
            *(float2*)&dst[(size_t)(r + 8) * HS + col] = o1;
        }
    }
}

// ---------------------------------------------------------------------------
// Kernel 2: causal flash attention, fp32 SIMT.
// 32-query tiles -> grid (64, 8) = 512 CTAs.
// 256 threads (16x16): ty -> 2 query rows, tx -> 4 key cols / 4 hs cols.
// ---------------------------------------------------------------------------
__global__ __launch_bounds__(256) void attn_kernel(float* __restrict__ out)
{
    const int qt = (TT / 32 - 1) - blockIdx.x;   // big tiles first
    const int b  = blockIdx.y;
    const int q0 = qt * 32;
    const int kt_last = qt >> 1;                 // last 64-key tile index

    __shared__ float Qt[64][32];    // [hs][q] transposed, pre-scaled
    __shared__ float KtP[64][64];   // K as [hs][key]; reused as P[32][64]
    __shared__ float Vs[64][64];    // [key][hs]

    const int tid = threadIdx.x;
    const int tx = tid & 15;
    const int ty = tid >> 4;

    {
        const float* qbase = g_q + ((size_t)b * TT + q0) * HS;
        #pragma unroll
        for (int p = 0; p < 2; p++) {
            int t = p * 256 + tid;     // 0..511
            int r = t >> 4;            // 0..31 query row
            int c4 = (t & 15) * 4;     // hs col
            float4 v = *(const float4*)&qbase[(size_t)r * HS + c4];
            Qt[c4 + 0][r] = v.x * 0.125f;
            Qt[c4 + 1][r] = v.y * 0.125f;
            Qt[c4 + 2][r] = v.z * 0.125f;
            Qt[c4 + 3][r] = v.w * 0.125f;
        }
    }

    float O[2][4];
    #pragma unroll
    for (int i = 0; i < 2; i++)
        #pragma unroll
        for (int j = 0; j < 4; j++) O[i][j] = 0.0f;
    float mrow[2] = {-1e30f, -1e30f};
    float lrow[2] = {0.0f, 0.0f};

    for (int kb = 0; kb <= kt_last; kb++) {
        __syncthreads();

        {
            const float* kbase = g_k + ((size_t)b * TT + kb * 64) * HS;
            const float* vbase = g_v + ((size_t)b * TT + kb * 64) * HS;
            #pragma unroll
            for (int p = 0; p < 4; p++) {
                int t = p * 256 + tid;
                int r = t >> 4;
                int c4 = (t & 15) * 4;
                float4 kv = *(const float4*)&kbase[(size_t)r * HS + c4];
                KtP[c4 + 0][r] = kv.x;
                KtP[c4 + 1][r] = kv.y;
                KtP[c4 + 2][r] = kv.z;
                KtP[c4 + 3][r] = kv.w;
                *(float4*)&Vs[r][c4] = *(const float4*)&vbase[(size_t)r * HS + c4];
            }
        }
        __syncthreads();

        // S = Q K^T  (2x4 per thread)
        float s[2][4];
        #pragma unroll
        for (int i = 0; i < 2; i++)
            #pragma unroll
            for (int j = 0; j < 4; j++) s[i][j] = 0.0f;

        #pragma unroll 16
        for (int k = 0; k < 64; k++) {
            float2 qa = *(float2*)&Qt[k][ty * 2];
            float4 kv = *(float4*)&KtP[k][tx * 4];
            s[0][0] += qa.x * kv.x; s[0][1] += qa.x * kv.y;
            s[0][2] += qa.x * kv.z; s[0][3] += qa.x * kv.w;
            s[1][0] += qa.y * kv.x; s[1][1] += qa.y * kv.y;
            s[1][2] += qa.y * kv.z; s[1][3] += qa.y * kv.w;
        }
        __syncthreads();   // K reads done before P overwrite

        if (kb == kt_last) {
            #pragma unroll
            for (int i = 0; i < 2; i++)
                #pragma unroll
                for (int j = 0; j < 4; j++)
                    if (kb * 64 + tx * 4 + j > q0 + ty * 2 + i) s[i][j] = -1e30f;
        }

        // online softmax per row group (16 tx threads via shfl)
        #pragma unroll
        for (int i = 0; i < 2; i++) {
            float mx = fmaxf(fmaxf(s[i][0], s[i][1]), fmaxf(s[i][2], s[i][3]));
            #pragma unroll
            for (int o = 8; o >= 1; o >>= 1)
                mx = fmaxf(mx, __shfl_xor_sync(0xffffffffu, mx, o));
            float mnew = fmaxf(mrow[i], mx);
            float alpha = __expf(mrow[i] - mnew);
            float sum = 0.0f;
            #pragma unroll
            for (int j = 0; j < 4; j++) {
                s[i][j] = __expf(s[i][j] - mnew);
                sum += s[i][j];
            }
            #pragma unroll
            for (int o = 8; o >= 1; o >>= 1)
                sum += __shfl_xor_sync(0xffffffffu, sum, o);
            lrow[i] = lrow[i] * alpha + sum;
            mrow[i] = mnew;
            #pragma unroll
            for (int j = 0; j < 4; j++) O[i][j] *= alpha;
            *(float4*)&KtP[ty * 2 + i][tx * 4] =
                make_float4(s[i][0], s[i][1], s[i][2], s[i][3]);
        }
        __syncthreads();

        // O += P @ V
        #pragma unroll
        for (int jj = 0; jj < 16; jj++) {
            float4 pv[2];
            pv[0] = *(float4*)&KtP[ty * 2 + 0][jj * 4];
            pv[1] = *(float4*)&KtP[ty * 2 + 1][jj * 4];
            float4 vv[4];
            #pragma unroll
            for (int j2 = 0; j2 < 4; j2++)
                vv[j2] = *(float4*)&Vs[jj * 4 + j2][tx * 4];
            #pragma unroll
            for (int i = 0; i < 2; i++) {
                float p0 = pv[i].x, p1 = pv[i].y, p2 = pv[i].z, p3 = pv[i].w;
                O[i][0] += p0 * vv[0].x + p1 * vv[1].x + p2 * vv[2].x + p3 * vv[3].x;
                O[i][1] += p0 * vv[0].y + p1 * vv[1].y + p2 * vv[2].y + p3 * vv[3].y;
                O[i][2] += p0 * vv[0].z + p1 * vv[1].z + p2 * vv[2].z + p3 * vv[3].z;
                O[i][3] += p0 * vv[0].w + p1 * vv[1].w + p2 * vv[2].w + p3 * vv[3].w;
            }
        }
    }

    float* obase = out + ((size_t)b * TT + q0) * HS;
    #pragma unroll
    for (int i = 0; i < 2; i++) {
        float inv = 1.0f / lrow[i];
        float4 o;
        o.x = O[i][0] * inv;
        o.y = O[i][1] * inv;
        o.z = O[i][2] * inv;
        o.w = O[i][3] * inv;
        *(float4*)&obase[(size_t)(ty * 2 + i) * HS + tx * 4] = o;
    }
}

// ---------------------------------------------------------------------------
extern "C" void kernel_launch(void* const* d_in, const int* in_sizes, int n_in,
                              void* d_out, int out_size)
{
    const float* X  = (const float*)d_in[0];
    const float* Wq = (const float*)d_in[1];
    const float* bq = (const float*)d_in[2];
    const float* Wk = (const float*)d_in[3];
    const float* bk = (const float*)d_in[4];
    const float* Wv = (const float*)d_in[5];
    const float* bv = (const float*)d_in[6];
    float* out = (float*)d_out;

    static int smem_set = 0;
    if (!smem_set) {
        cudaFuncSetAttribute(qkv_mma_kernel,
                             cudaFuncAttributeMaxDynamicSharedMemorySize,
                             SMEM_QKV);
        smem_set = 1;
    }

    w_convert_kernel<<<192, 256>>>(Wq, Wk, Wv);
    qkv_mma_kernel<<<128, 256, SMEM_QKV>>>(X, bq, bk, bv);

    dim3 g2(TT / 32, BB);                // (64, 8)
    attn_kernel<<<g2, 256>>>(out);
}

// round 4
// speedup vs baseline: 3.0507x; 2.0429x over previous
#include <cuda_runtime.h>
#include <cuda_bf16.h>
#include <cstdint>

#define BB 8
#define TT 2048
#define EE 1024
#define HS 64
#define NTOT 192   // q(64) | k(64) | v(64)

// Scratch
__device__ float g_q[BB * TT * HS];
__device__ float g_k[BB * TT * HS];
__device__ float g_v[BB * TT * HS];
__device__ __nv_bfloat16 g_Wh[NTOT * EE];
__device__ __nv_bfloat16 g_Wl[NTOT * EE];

// ---------------------------------------------------------------------------
// Helpers
// ---------------------------------------------------------------------------
__device__ __forceinline__ uint32_t smem_u32(const void* p) {
    uint32_t a;
    asm("{ .reg .u64 t; cvta.to.shared.u64 t, %1; cvt.u32.u64 %0, t; }"
        : "=r"(a) : "l"(p));
    return a;
}

__device__ __forceinline__ void cp16(uint32_t dst, const void* src) {
    asm volatile("cp.async.cg.shared.global [%0], [%1], 16;"
                 :: "r"(dst), "l"(src));
}

__device__ __forceinline__ void mma16816(float* c, const uint32_t* a,
                                         const uint32_t* b) {
    asm volatile(
        "mma.sync.aligned.m16n8k16.row.col.f32.bf16.bf16.f32 "
        "{%0,%1,%2,%3}, {%4,%5,%6,%7}, {%8,%9}, {%0,%1,%2,%3};"
        : "+f"(c[0]), "+f"(c[1]), "+f"(c[2]), "+f"(c[3])
        : "r"(a[0]), "r"(a[1]), "r"(a[2]), "r"(a[3]), "r"(b[0]), "r"(b[1]));
}

// hi/lo bf16 split of a float4
__device__ __forceinline__ void split4(float4 v, uint2& hi, uint2& lo) {
    __nv_bfloat162 h0 = __floats2bfloat162_rn(v.x, v.y);
    __nv_bfloat162 h1 = __floats2bfloat162_rn(v.z, v.w);
    float2 f0 = __bfloat1622float2(h0);
    float2 f1 = __bfloat1622float2(h1);
    __nv_bfloat162 l0 = __floats2bfloat162_rn(v.x - f0.x, v.y - f0.y);
    __nv_bfloat162 l1 = __floats2bfloat162_rn(v.z - f1.x, v.w - f1.y);
    hi.x = *(uint32_t*)&h0; hi.y = *(uint32_t*)&h1;
    lo.x = *(uint32_t*)&l0; lo.y = *(uint32_t*)&l1;
}

// ---------------------------------------------------------------------------
// Kernel 0: convert concat(Wq,Wk,Wv) fp32 -> bf16 hi/lo, row-major [192][1024]
// ---------------------------------------------------------------------------
__global__ __launch_bounds__(256) void w_convert_kernel(
    const float* __restrict__ Wq, const float* __restrict__ Wk,
    const float* __restrict__ Wv)
{
    int idx = blockIdx.x * 256 + threadIdx.x;
    int e4 = idx * 4;
    int n = e4 >> 10;
    int c = e4 & 1023;
    const float* src = (n < 64) ? &Wq[n * 1024 + c]
                     : (n < 128) ? &Wk[(n - 64) * 1024 + c]
                     : &Wv[(n - 128) * 1024 + c];
    float4 v = *(const float4*)src;
    uint2 hi, lo;
    split4(v, hi, lo);
    *(uint2*)&g_Wh[e4] = hi;
    *(uint2*)&g_Wl[e4] = lo;
}

// ---------------------------------------------------------------------------
// Kernel 1: QKV projection via mma.sync bf16 (3-term hi/lo split). Unchanged.
// ---------------------------------------------------------------------------
#define STAGE 40960
#define BOFF  16384
#define SMEM_QKV (2 * STAGE)

__global__ void __launch_bounds__(256) qkv_mma_kernel(
    const float* __restrict__ X,
    const float* __restrict__ bq, const float* __restrict__ bk,
    const float* __restrict__ bv)
{
    extern __shared__ __align__(128) char sm[];
    const uint32_t smb = smem_u32(sm);
    const int tid = threadIdx.x;
    const int lid = tid & 31;
    const int wid = tid >> 5;
    const int wm  = wid >> 2;
    const int wn  = wid & 3;
    const int lg  = lid >> 2;
    const int lt  = lid & 3;
    const int m0  = blockIdx.x * 128;

    float acc[4][6][4];
    #pragma unroll
    for (int t = 0; t < 4; t++)
        #pragma unroll
        for (int u = 0; u < 6; u++)
            #pragma unroll
            for (int r = 0; r < 4; r++) acc[t][u][r] = 0.0f;

    float4 xr[4];

    {
        const int k0 = 0;
        #pragma unroll
        for (int p = 0; p < 4; p++) {
            int i = p * 256 + tid;
            int row = i >> 3, c4 = (i & 7) * 4;
            xr[p] = *(const float4*)&X[(size_t)(m0 + row) * EE + k0 + c4];
        }
        #pragma unroll
        for (int j = 0; j < 6; j++) {
            int idx = j * 256 + tid;
            int n = idx >> 3, u = idx & 7;
            int kg = u & 3, wh = u >> 2;
            const __nv_bfloat16* s =
                (wh ? g_Wl : g_Wh) + n * EE + k0 + kg * 8;
            cp16(smb + BOFF + n * 128 + ((u ^ (n & 7)) * 16), s);
        }
        asm volatile("cp.async.commit_group;");
        #pragma unroll
        for (int p = 0; p < 4; p++) {
            int i = p * 256 + tid;
            int row = i >> 3, c4 = (i & 7) * 4;
            int kg = c4 >> 3, bo = (c4 & 4) * 2;
            uint2 hi, lo;
            split4(xr[p], hi, lo);
            *(uint2*)(sm + row * 128 + ((kg ^ (row & 7)) * 16) + bo) = hi;
            *(uint2*)(sm + row * 128 + (((kg | 4) ^ (row & 7)) * 16) + bo) = lo;
        }
        asm volatile("cp.async.wait_group 0;");
        __syncthreads();
    }

    for (int c = 0; c < 32; c++) {
        const int cb = c & 1;
        const int nb = (c + 1) & 1;
        if (c < 31) {
            const int k0 = (c + 1) * 32;
            #pragma unroll
            for (int p = 0; p < 4; p++) {
                int i = p * 256 + tid;
                int row = i >> 3, c4 = (i & 7) * 4;
                xr[p] = *(const float4*)&X[(size_t)(m0 + row) * EE + k0 + c4];
            }
            #pragma unroll
            for (int j = 0; j < 6; j++) {
                int idx = j * 256 + tid;
                int n = idx >> 3, u = idx & 7;
                int kg = u & 3, wh = u >> 2;
                const __nv_bfloat16* s =
                    (wh ? g_Wl : g_Wh) + n * EE + k0 + kg * 8;
                cp16(smb + nb * STAGE + BOFF + n * 128 + ((u ^ (n & 7)) * 16), s);
            }
            asm volatile("cp.async.commit_group;");
        }

        const char* ab = sm + cb * STAGE;
        const char* bb = ab + BOFF;
        #pragma unroll
        for (int h = 0; h < 2; h++) {
            uint32_t afh[4][4], afl[4][4], bfh[6][2], bfl[6][2];
            #pragma unroll
            for (int t = 0; t < 4; t++) {
                int r  = wm * 64 + t * 16 + lg;
                int r8 = r + 8;
                int kg0 = 2 * h, kg1 = 2 * h + 1;
                afh[t][0] = *(const uint32_t*)(ab + r  * 128 + ((kg0 ^ (r  & 7)) * 16) + lt * 4);
                afh[t][1] = *(const uint32_t*)(ab + r8 * 128 + ((kg0 ^ (r8 & 7)) * 16) + lt * 4);
                afh[t][2] = *(const uint32_t*)(ab + r  * 128 + ((kg1 ^ (r  & 7)) * 16) + lt * 4);
                afh[t][3] = *(const uint32_t*)(ab + r8 * 128 + ((kg1 ^ (r8 & 7)) * 16) + lt * 4);
                afl[t][0] = *(const uint32_t*)(ab + r  * 128 + (((kg0 | 4) ^ (r  & 7)) * 16) + lt * 4);
                afl[t][1] = *(const uint32_t*)(ab + r8 * 128 + (((kg0 | 4) ^ (r8 & 7)) * 16) + lt * 4);
                afl[t][2] = *(const uint32_t*)(ab + r  * 128 + (((kg1 | 4) ^ (r  & 7)) * 16) + lt * 4);
                afl[t][3] = *(const uint32_t*)(ab + r8 * 128 + (((kg1 | 4) ^ (r8 & 7)) * 16) + lt * 4);
            }
            #pragma unroll
            for (int u = 0; u < 6; u++) {
                int n = wn * 48 + u * 8 + lg;
                int kg0 = 2 * h, kg1 = 2 * h + 1;
                bfh[u][0] = *(const uint32_t*)(bb + n * 128 + ((kg0 ^ (n & 7)) * 16) + lt * 4);
                bfh[u][1] = *(const uint32_t*)(bb + n * 128 + ((kg1 ^ (n & 7)) * 16) + lt * 4);
                bfl[u][0] = *(const uint32_t*)(bb + n * 128 + (((kg0 | 4) ^ (n & 7)) * 16) + lt * 4);
                bfl[u][1] = *(const uint32_t*)(bb + n * 128 + (((kg1 | 4) ^ (n & 7)) * 16) + lt * 4);
            }
            #pragma unroll
            for (int t = 0; t < 4; t++)
                #pragma unroll
                for (int u = 0; u < 6; u++)
                    mma16816(acc[t][u], afh[t], bfh[u]);
            #pragma unroll
            for (int t = 0; t < 4; t++)
                #pragma unroll
                for (int u = 0; u < 6; u++)
                    mma16816(acc[t][u], afh[t], bfl[u]);
            #pragma unroll
            for (int t = 0; t < 4; t++)
                #pragma unroll
                for (int u = 0; u < 6; u++)
                    mma16816(acc[t][u], afl[t], bfh[u]);
        }

        if (c < 31) {
            #pragma unroll
            for (int p = 0; p < 4; p++) {
                int i = p * 256 + tid;
                int row = i >> 3, c4 = (i & 7) * 4;
                int kg = c4 >> 3, bo = (c4 & 4) * 2;
                uint2 hi, lo;
                split4(xr[p], hi, lo);
                *(uint2*)(sm + nb * STAGE + row * 128 + ((kg ^ (row & 7)) * 16) + bo) = hi;
                *(uint2*)(sm + nb * STAGE + row * 128 + (((kg | 4) ^ (row & 7)) * 16) + bo) = lo;
            }
            asm volatile("cp.async.wait_group 0;");
        }
        __syncthreads();
    }

    #pragma unroll
    for (int t = 0; t < 4; t++) {
        int r = m0 + wm * 64 + t * 16 + lg;
        #pragma unroll
        for (int u = 0; u < 6; u++) {
            int n = wn * 48 + u * 8 + lt * 2;
            float* dst;
            int col;
            const float* barr;
            if (n < 64)       { dst = g_q; col = n;       barr = bq; }
            else if (n < 128) { dst = g_k; col = n - 64;  barr = bk; }
            else              { dst = g_v; col = n - 128; barr = bv; }
            float b0 = __ldg(&barr[col]);
            float b1 = __ldg(&barr[col + 1]);
            float2 o0 = make_float2(acc[t][u][0] + b0, acc[t][u][1] + b1);
            float2 o1 = make_float2(acc[t][u][2] + b0, acc[t][u][3] + b1);
            *(float2*)&dst[(size_t)r * HS + col] = o0;
            *(float2*)&dst[(size_t)(r + 8) * HS + col] = o1;
        }
    }
}

// ---------------------------------------------------------------------------
// Kernel 2: causal flash attention via mma.sync bf16 (hi/lo 3-term on both
// S=QK^T and O=PV).  64-query tiles, 128 threads (4 warps x 16 rows).
// Grid (32, 8), biggest tile first (LPT).  2 CTAs/SM resident.
//
// smem layout (36,864B static):
//   Kh/Kl:  [64 key][72 bf16]  (row-major, pad->conflict-free LDS.32 B-frags)
//           (also used to stage Q hi/lo before the key loop)
//   Vph/Vpl:[32 kp][72 u32]    key-pair packed: word = bf16x2(V[2kp][h],V[2kp+1][h])
// Q a-frags and P a-frags (S accum relayout) live in registers.
// ---------------------------------------------------------------------------
#define ATS 72           // row stride: 72 bf16 (K) / 72 u32 (Vp)

__global__ void __launch_bounds__(128) attn_mma_kernel(float* __restrict__ out)
{
    __shared__ __align__(16) __nv_bfloat16 Kh[64 * ATS];
    __shared__ __align__(16) __nv_bfloat16 Kl[64 * ATS];
    __shared__ __align__(16) uint32_t Vph[32 * ATS];
    __shared__ __align__(16) uint32_t Vpl[32 * ATS];

    const int qt = 31 - blockIdx.x;        // biggest first
    const int b  = blockIdx.y;
    const int q0 = qt * 64;
    const int tid  = threadIdx.x;
    const int lane = tid & 31;
    const int w    = tid >> 5;
    const int lg   = lane >> 2;
    const int lt   = lane & 3;
    const int wrow = w * 16;               // warp's query-row base in tile

    // ---- stage Q (scaled by 0.125) into Kh/Kl, then pull a-frags to regs
    {
        const float* qb = g_q + ((size_t)b * TT + q0) * HS;
        #pragma unroll
        for (int i = 0; i < 8; i++) {
            int idx = i * 128 + tid;
            int r = idx >> 4, c4 = (idx & 15) * 4;
            float4 v = *(const float4*)&qb[r * HS + c4];
            v.x *= 0.125f; v.y *= 0.125f; v.z *= 0.125f; v.w *= 0.125f;
            uint2 hi, lo;
            split4(v, hi, lo);
            *(uint2*)&Kh[r * ATS + c4] = hi;
            *(uint2*)&Kl[r * ATS + c4] = lo;
        }
    }
    __syncthreads();

    uint32_t qh[4][4], ql[4][4];
    #pragma unroll
    for (int kk = 0; kk < 4; kk++) {
        int h0 = kk * 16 + 2 * lt;
        qh[kk][0] = *(const uint32_t*)&Kh[(wrow + lg) * ATS + h0];
        qh[kk][1] = *(const uint32_t*)&Kh[(wrow + lg + 8) * ATS + h0];
        qh[kk][2] = *(const uint32_t*)&Kh[(wrow + lg) * ATS + h0 + 8];
        qh[kk][3] = *(const uint32_t*)&Kh[(wrow + lg + 8) * ATS + h0 + 8];
        ql[kk][0] = *(const uint32_t*)&Kl[(wrow + lg) * ATS + h0];
        ql[kk][1] = *(const uint32_t*)&Kl[(wrow + lg + 8) * ATS + h0];
        ql[kk][2] = *(const uint32_t*)&Kl[(wrow + lg) * ATS + h0 + 8];
        ql[kk][3] = *(const uint32_t*)&Kl[(wrow + lg + 8) * ATS + h0 + 8];
    }
    __syncthreads();

    float O[8][4];
    #pragma unroll
    for (int j = 0; j < 8; j++)
        #pragma unroll
        for (int e = 0; e < 4; e++) O[j][e] = 0.0f;
    float m0 = -1e30f, m1 = -1e30f, l0 = 0.0f, l1 = 0.0f;

    for (int kt = 0; kt <= qt; kt++) {
        // ---- load K tile -> Kh/Kl
        {
            const float* kb = g_k + ((size_t)b * TT + kt * 64) * HS;
            #pragma unroll
            for (int i = 0; i < 8; i++) {
                int idx = i * 128 + tid;
                int r = idx >> 4, c4 = (idx & 15) * 4;
                float4 v = *(const float4*)&kb[r * HS + c4];
                uint2 hi, lo;
                split4(v, hi, lo);
                *(uint2*)&Kh[r * ATS + c4] = hi;
                *(uint2*)&Kl[r * ATS + c4] = lo;
            }
        }
        // ---- load V tile -> key-pair packed Vph/Vpl
        {
            const float* vb = g_v + ((size_t)b * TT + kt * 64) * HS;
            #pragma unroll
            for (int i = 0; i < 4; i++) {
                int kp = i * 8 + (tid >> 4);
                int c4 = (tid & 15) * 4;
                float4 v0 = *(const float4*)&vb[(2 * kp) * HS + c4];
                float4 v1 = *(const float4*)&vb[(2 * kp + 1) * HS + c4];
                float a0[4] = {v0.x, v0.y, v0.z, v0.w};
                float a1[4] = {v1.x, v1.y, v1.z, v1.w};
                uint32_t ph_[4], pl_[4];
                #pragma unroll
                for (int j = 0; j < 4; j++) {
                    __nv_bfloat162 h = __floats2bfloat162_rn(a0[j], a1[j]);
                    float2 hf = __bfloat1622float2(h);
                    __nv_bfloat162 l =
                        __floats2bfloat162_rn(a0[j] - hf.x, a1[j] - hf.y);
                    ph_[j] = *(uint32_t*)&h;
                    pl_[j] = *(uint32_t*)&l;
                }
                *(uint4*)&Vph[kp * ATS + c4] = make_uint4(ph_[0], ph_[1], ph_[2], ph_[3]);
                *(uint4*)&Vpl[kp * ATS + c4] = make_uint4(pl_[0], pl_[1], pl_[2], pl_[3]);
            }
        }
        __syncthreads();

        // ---- S = Q K^T (3-term), fp32 accum
        float s[8][4];
        #pragma unroll
        for (int j = 0; j < 8; j++)
            #pragma unroll
            for (int e = 0; e < 4; e++) s[j][e] = 0.0f;

        #pragma unroll
        for (int kk = 0; kk < 4; kk++) {
            int h0 = kk * 16 + 2 * lt;
            #pragma unroll
            for (int j = 0; j < 8; j++) {
                int key = j * 8 + lg;
                uint32_t bh[2], bl[2];
                bh[0] = *(const uint32_t*)&Kh[key * ATS + h0];
                bh[1] = *(const uint32_t*)&Kh[key * ATS + h0 + 8];
                bl[0] = *(const uint32_t*)&Kl[key * ATS + h0];
                bl[1] = *(const uint32_t*)&Kl[key * ATS + h0 + 8];
                mma16816(s[j], qh[kk], bh);
                mma16816(s[j], qh[kk], bl);
                mma16816(s[j], ql[kk], bh);
            }
        }

        // ---- causal mask (diagonal tile only)
        if (kt == qt) {
            #pragma unroll
            for (int j = 0; j < 8; j++) {
                int lc = j * 8 + 2 * lt;
                int r0 = wrow + lg, r1 = r0 + 8;
                if (lc > r0)     s[j][0] = -1e30f;
                if (lc + 1 > r0) s[j][1] = -1e30f;
                if (lc > r1)     s[j][2] = -1e30f;
                if (lc + 1 > r1) s[j][3] = -1e30f;
            }
        }

        // ---- online softmax (rows lg -> m0/l0, lg+8 -> m1/l1)
        {
            float mx0 = -1e30f, mx1 = -1e30f;
            #pragma unroll
            for (int j = 0; j < 8; j++) {
                mx0 = fmaxf(mx0, fmaxf(s[j][0], s[j][1]));
                mx1 = fmaxf(mx1, fmaxf(s[j][2], s[j][3]));
            }
            #pragma unroll
            for (int o = 1; o <= 2; o <<= 1) {
                mx0 = fmaxf(mx0, __shfl_xor_sync(0xffffffffu, mx0, o));
                mx1 = fmaxf(mx1, __shfl_xor_sync(0xffffffffu, mx1, o));
            }
            float mn0 = fmaxf(m0, mx0), mn1 = fmaxf(m1, mx1);
            float al0 = __expf(m0 - mn0), al1 = __expf(m1 - mn1);
            float sum0 = 0.0f, sum1 = 0.0f;
            #pragma unroll
            for (int j = 0; j < 8; j++) {
                s[j][0] = __expf(s[j][0] - mn0);
                s[j][1] = __expf(s[j][1] - mn0);
                s[j][2] = __expf(s[j][2] - mn1);
                s[j][3] = __expf(s[j][3] - mn1);
                sum0 += s[j][0] + s[j][1];
                sum1 += s[j][2] + s[j][3];
            }
            #pragma unroll
            for (int o = 1; o <= 2; o <<= 1) {
                sum0 += __shfl_xor_sync(0xffffffffu, sum0, o);
                sum1 += __shfl_xor_sync(0xffffffffu, sum1, o);
            }
            l0 = l0 * al0 + sum0;
            l1 = l1 * al1 + sum1;
            m0 = mn0; m1 = mn1;
            #pragma unroll
            for (int j = 0; j < 8; j++) {
                O[j][0] *= al0; O[j][1] *= al0;
                O[j][2] *= al1; O[j][3] *= al1;
            }
        }

        // ---- pack P hi/lo (S accum -> A-frag layout)
        uint32_t ph[8][2], pl[8][2];
        #pragma unroll
        for (int j = 0; j < 8; j++) {
            __nv_bfloat162 h01 = __floats2bfloat162_rn(s[j][0], s[j][1]);
            __nv_bfloat162 h23 = __floats2bfloat162_rn(s[j][2], s[j][3]);
            float2 f01 = __bfloat1622float2(h01);
            float2 f23 = __bfloat1622float2(h23);
            __nv_bfloat162 q01 =
                __floats2bfloat162_rn(s[j][0] - f01.x, s[j][1] - f01.y);
            __nv_bfloat162 q23 =
                __floats2bfloat162_rn(s[j][2] - f23.x, s[j][3] - f23.y);
            ph[j][0] = *(uint32_t*)&h01; ph[j][1] = *(uint32_t*)&h23;
            pl[j][0] = *(uint32_t*)&q01; pl[j][1] = *(uint32_t*)&q23;
        }

        // ---- O += P @ V (3-term)
        #pragma unroll
        for (int jh = 0; jh < 8; jh++) {
            int h = jh * 8 + lg;
            #pragma unroll
            for (int kk = 0; kk < 4; kk++) {
                uint32_t vh[2], vl[2];
                vh[0] = Vph[(kk * 8 + lt) * ATS + h];
                vh[1] = Vph[(kk * 8 + 4 + lt) * ATS + h];
                vl[0] = Vpl[(kk * 8 + lt) * ATS + h];
                vl[1] = Vpl[(kk * 8 + 4 + lt) * ATS + h];
                uint32_t aH[4] = {ph[2 * kk][0], ph[2 * kk][1],
                                  ph[2 * kk + 1][0], ph[2 * kk + 1][1]};
                uint32_t aL[4] = {pl[2 * kk][0], pl[2 * kk][1],
                                  pl[2 * kk + 1][0], pl[2 * kk + 1][1]};
                mma16816(O[jh], aH, vh);
                mma16816(O[jh], aH, vl);
                mma16816(O[jh], aL, vh);
            }
        }
        __syncthreads();   // done reading K/V before next tile overwrites
    }

    // ---- epilogue
    float inv0 = 1.0f / l0, inv1 = 1.0f / l1;
    float* ob = out + ((size_t)b * TT + q0) * HS;
    #pragma unroll
    for (int jh = 0; jh < 8; jh++) {
        int hcol = jh * 8 + 2 * lt;
        *(float2*)&ob[(size_t)(wrow + lg) * HS + hcol] =
            make_float2(O[jh][0] * inv0, O[jh][1] * inv0);
        *(float2*)&ob[(size_t)(wrow + lg + 8) * HS + hcol] =
            make_float2(O[jh][2] * inv1, O[jh][3] * inv1);
    }
}

// ---------------------------------------------------------------------------
extern "C" void kernel_launch(void* const* d_in, const int* in_sizes, int n_in,
                              void* d_out, int out_size)
{
    const float* X  = (const float*)d_in[0];
    const float* Wq = (const float*)d_in[1];
    const float* bq = (const float*)d_in[2];
    const float* Wk = (const float*)d_in[3];
    const float* bk = (const float*)d_in[4];
    const float* Wv = (const float*)d_in[5];
    const float* bv = (const float*)d_in[6];
    float* out = (float*)d_out;

    static int smem_set = 0;
    if (!smem_set) {
        cudaFuncSetAttribute(qkv_mma_kernel,
                             cudaFuncAttributeMaxDynamicSharedMemorySize,
                             SMEM_QKV);
        smem_set = 1;
    }

    w_convert_kernel<<<192, 256>>>(Wq, Wk, Wv);
    qkv_mma_kernel<<<128, 256, SMEM_QKV>>>(X, bq, bk, bv);

    dim3 g2(TT / 64, BB);                // (32, 8)
    attn_mma_kernel<<<g2, 128>>>(out);
}

// round 5
// speedup vs baseline: 3.8413x; 1.2591x over previous
#include <cuda_runtime.h>
#include <cuda_bf16.h>
#include <cstdint>

#define BB 8
#define TT 2048
#define EE 1024
#define HS 64
#define NTOT 192   // q(64) | k(64) | v(64)
#define ROWS (BB * TT)
#define PSTRIDE (BB * TT * HS)

// Preconverted operands (written by qkv epilogue)
__device__ __nv_bfloat16 g_qh[ROWS * HS];   // Q hi, pre-scaled 0.125, [B*T][64]
__device__ __nv_bfloat16 g_ql[ROWS * HS];
__device__ __nv_bfloat16 g_kh[ROWS * HS];   // K hi [B*T][64]
__device__ __nv_bfloat16 g_kl[ROWS * HS];
__device__ __nv_bfloat16 g_vth[BB * HS * TT];  // V transposed [B][64h][2048t]
__device__ __nv_bfloat16 g_vtl[BB * HS * TT];
// Weights bf16 hi/lo
__device__ __nv_bfloat16 g_Wh[NTOT * EE];
__device__ __nv_bfloat16 g_Wl[NTOT * EE];
// Attention partials (2 key-split parts)
__device__ float g_pO[2 * PSTRIDE];
__device__ float g_pm[2 * ROWS];
__device__ float g_pl[2 * ROWS];

// ---------------------------------------------------------------------------
// Helpers
// ---------------------------------------------------------------------------
__device__ __forceinline__ uint32_t smem_u32(const void* p) {
    uint32_t a;
    asm("{ .reg .u64 t; cvta.to.shared.u64 t, %1; cvt.u32.u64 %0, t; }"
        : "=r"(a) : "l"(p));
    return a;
}

__device__ __forceinline__ void cp16(uint32_t dst, const void* src) {
    asm volatile("cp.async.cg.shared.global [%0], [%1], 16;"
                 :: "r"(dst), "l"(src));
}

__device__ __forceinline__ void mma16816(float* c, const uint32_t* a,
                                         const uint32_t* b) {
    asm volatile(
        "mma.sync.aligned.m16n8k16.row.col.f32.bf16.bf16.f32 "
        "{%0,%1,%2,%3}, {%4,%5,%6,%7}, {%8,%9}, {%0,%1,%2,%3};"
        : "+f"(c[0]), "+f"(c[1]), "+f"(c[2]), "+f"(c[3])
        : "r"(a[0]), "r"(a[1]), "r"(a[2]), "r"(a[3]), "r"(b[0]), "r"(b[1]));
}

// hi/lo bf16 split of a float4
__device__ __forceinline__ void split4(float4 v, uint2& hi, uint2& lo) {
    __nv_bfloat162 h0 = __floats2bfloat162_rn(v.x, v.y);
    __nv_bfloat162 h1 = __floats2bfloat162_rn(v.z, v.w);
    float2 f0 = __bfloat1622float2(h0);
    float2 f1 = __bfloat1622float2(h1);
    __nv_bfloat162 l0 = __floats2bfloat162_rn(v.x - f0.x, v.y - f0.y);
    __nv_bfloat162 l1 = __floats2bfloat162_rn(v.z - f1.x, v.w - f1.y);
    hi.x = *(uint32_t*)&h0; hi.y = *(uint32_t*)&h1;
    lo.x = *(uint32_t*)&l0; lo.y = *(uint32_t*)&l1;
}

// ---------------------------------------------------------------------------
// Kernel 0: convert concat(Wq,Wk,Wv) fp32 -> bf16 hi/lo
// ---------------------------------------------------------------------------
__global__ __launch_bounds__(256) void w_convert_kernel(
    const float* __restrict__ Wq, const float* __restrict__ Wk,
    const float* __restrict__ Wv)
{
    int idx = blockIdx.x * 256 + threadIdx.x;
    int e4 = idx * 4;
    int n = e4 >> 10;
    int c = e4 & 1023;
    const float* src = (n < 64) ? &Wq[n * 1024 + c]
                     : (n < 128) ? &Wk[(n - 64) * 1024 + c]
                     : &Wv[(n - 128) * 1024 + c];
    float4 v = *(const float4*)src;
    uint2 hi, lo;
    split4(v, hi, lo);
    *(uint2*)&g_Wh[e4] = hi;
    *(uint2*)&g_Wl[e4] = lo;
}

// ---------------------------------------------------------------------------
// Kernel 1: QKV projection (mma.sync bf16, 3-term).  Epilogue now emits
// bf16 hi/lo Q (scaled), K, and smem-transposed V.
// ---------------------------------------------------------------------------
#define STAGE 40960
#define BOFF  16384
#define SMEM_QKV (2 * STAGE)

__global__ void __launch_bounds__(256) qkv_mma_kernel(
    const float* __restrict__ X,
    const float* __restrict__ bq, const float* __restrict__ bk,
    const float* __restrict__ bv)
{
    extern __shared__ __align__(128) char sm[];
    const uint32_t smb = smem_u32(sm);
    const int tid = threadIdx.x;
    const int lid = tid & 31;
    const int wid = tid >> 5;
    const int wm  = wid >> 2;
    const int wn  = wid & 3;
    const int lg  = lid >> 2;
    const int lt  = lid & 3;
    const int m0  = blockIdx.x * 128;

    float acc[4][6][4];
    #pragma unroll
    for (int t = 0; t < 4; t++)
        #pragma unroll
        for (int u = 0; u < 6; u++)
            #pragma unroll
            for (int r = 0; r < 4; r++) acc[t][u][r] = 0.0f;

    float4 xr[4];

    {
        const int k0 = 0;
        #pragma unroll
        for (int p = 0; p < 4; p++) {
            int i = p * 256 + tid;
            int row = i >> 3, c4 = (i & 7) * 4;
            xr[p] = *(const float4*)&X[(size_t)(m0 + row) * EE + k0 + c4];
        }
        #pragma unroll
        for (int j = 0; j < 6; j++) {
            int idx = j * 256 + tid;
            int n = idx >> 3, u = idx & 7;
            int kg = u & 3, wh = u >> 2;
            const __nv_bfloat16* s =
                (wh ? g_Wl : g_Wh) + n * EE + k0 + kg * 8;
            cp16(smb + BOFF + n * 128 + ((u ^ (n & 7)) * 16), s);
        }
        asm volatile("cp.async.commit_group;");
        #pragma unroll
        for (int p = 0; p < 4; p++) {
            int i = p * 256 + tid;
            int row = i >> 3, c4 = (i & 7) * 4;
            int kg = c4 >> 3, bo = (c4 & 4) * 2;
            uint2 hi, lo;
            split4(xr[p], hi, lo);
            *(uint2*)(sm + row * 128 + ((kg ^ (row & 7)) * 16) + bo) = hi;
            *(uint2*)(sm + row * 128 + (((kg | 4) ^ (row & 7)) * 16) + bo) = lo;
        }
        asm volatile("cp.async.wait_group 0;");
        __syncthreads();
    }

    for (int c = 0; c < 32; c++) {
        const int cb = c & 1;
        const int nb = (c + 1) & 1;
        if (c < 31) {
            const int k0 = (c + 1) * 32;
            #pragma unroll
            for (int p = 0; p < 4; p++) {
                int i = p * 256 + tid;
                int row = i >> 3, c4 = (i & 7) * 4;
                xr[p] = *(const float4*)&X[(size_t)(m0 + row) * EE + k0 + c4];
            }
            #pragma unroll
            for (int j = 0; j < 6; j++) {
                int idx = j * 256 + tid;
                int n = idx >> 3, u = idx & 7;
                int kg = u & 3, wh = u >> 2;
                const __nv_bfloat16* s =
                    (wh ? g_Wl : g_Wh) + n * EE + k0 + kg * 8;
                cp16(smb + nb * STAGE + BOFF + n * 128 + ((u ^ (n & 7)) * 16), s);
            }
            asm volatile("cp.async.commit_group;");
        }

        const char* ab = sm + cb * STAGE;
        const char* bb = ab + BOFF;
        #pragma unroll
        for (int h = 0; h < 2; h++) {
            uint32_t afh[4][4], afl[4][4], bfh[6][2], bfl[6][2];
            #pragma unroll
            for (int t = 0; t < 4; t++) {
                int r  = wm * 64 + t * 16 + lg;
                int r8 = r + 8;
                int kg0 = 2 * h, kg1 = 2 * h + 1;
                afh[t][0] = *(const uint32_t*)(ab + r  * 128 + ((kg0 ^ (r  & 7)) * 16) + lt * 4);
                afh[t][1] = *(const uint32_t*)(ab + r8 * 128 + ((kg0 ^ (r8 & 7)) * 16) + lt * 4);
                afh[t][2] = *(const uint32_t*)(ab + r  * 128 + ((kg1 ^ (r  & 7)) * 16) + lt * 4);
                afh[t][3] = *(const uint32_t*)(ab + r8 * 128 + ((kg1 ^ (r8 & 7)) * 16) + lt * 4);
                afl[t][0] = *(const uint32_t*)(ab + r  * 128 + (((kg0 | 4) ^ (r  & 7)) * 16) + lt * 4);
                afl[t][1] = *(const uint32_t*)(ab + r8 * 128 + (((kg0 | 4) ^ (r8 & 7)) * 16) + lt * 4);
                afl[t][2] = *(const uint32_t*)(ab + r  * 128 + (((kg1 | 4) ^ (r  & 7)) * 16) + lt * 4);
                afl[t][3] = *(const uint32_t*)(ab + r8 * 128 + (((kg1 | 4) ^ (r8 & 7)) * 16) + lt * 4);
            }
            #pragma unroll
            for (int u = 0; u < 6; u++) {
                int n = wn * 48 + u * 8 + lg;
                int kg0 = 2 * h, kg1 = 2 * h + 1;
                bfh[u][0] = *(const uint32_t*)(bb + n * 128 + ((kg0 ^ (n & 7)) * 16) + lt * 4);
                bfh[u][1] = *(const uint32_t*)(bb + n * 128 + ((kg1 ^ (n & 7)) * 16) + lt * 4);
                bfl[u][0] = *(const uint32_t*)(bb + n * 128 + (((kg0 | 4) ^ (n & 7)) * 16) + lt * 4);
                bfl[u][1] = *(const uint32_t*)(bb + n * 128 + (((kg1 | 4) ^ (n & 7)) * 16) + lt * 4);
            }
            #pragma unroll
            for (int t = 0; t < 4; t++)
                #pragma unroll
                for (int u = 0; u < 6; u++)
                    mma16816(acc[t][u], afh[t], bfh[u]);
            #pragma unroll
            for (int t = 0; t < 4; t++)
                #pragma unroll
                for (int u = 0; u < 6; u++)
                    mma16816(acc[t][u], afh[t], bfl[u]);
            #pragma unroll
            for (int t = 0; t < 4; t++)
                #pragma unroll
                for (int u = 0; u < 6; u++)
                    mma16816(acc[t][u], afl[t], bfh[u]);
        }

        if (c < 31) {
            #pragma unroll
            for (int p = 0; p < 4; p++) {
                int i = p * 256 + tid;
                int row = i >> 3, c4 = (i & 7) * 4;
                int kg = c4 >> 3, bo = (c4 & 4) * 2;
                uint2 hi, lo;
                split4(xr[p], hi, lo);
                *(uint2*)(sm + nb * STAGE + row * 128 + ((kg ^ (row & 7)) * 16) + bo) = hi;
                *(uint2*)(sm + nb * STAGE + row * 128 + (((kg | 4) ^ (row & 7)) * 16) + bo) = lo;
            }
            asm volatile("cp.async.wait_group 0;");
        }
        __syncthreads();
    }

    // ---- epilogue: bias, convert to bf16 hi/lo; V transposed via smem
    __nv_bfloat16* VtSh = (__nv_bfloat16*)sm;            // [64h][128 rl]
    __nv_bfloat16* VtSl = (__nv_bfloat16*)(sm + 16384);

    #pragma unroll
    for (int t = 0; t < 4; t++) {
        int rl = wm * 64 + t * 16 + lg;            // local rows rl, rl+8
        size_t rg = (size_t)(m0 + rl);
        #pragma unroll
        for (int u = 0; u < 6; u++) {
            int n = wn * 48 + u * 8 + lt * 2;
            const float* barr; int col; int kind;
            if (n < 64)       { col = n;       barr = bq; kind = 0; }
            else if (n < 128) { col = n - 64;  barr = bk; kind = 1; }
            else              { col = n - 128; barr = bv; kind = 2; }
            float b0 = __ldg(&barr[col]), b1 = __ldg(&barr[col + 1]);
            float v00 = acc[t][u][0] + b0, v01 = acc[t][u][1] + b1;
            float v10 = acc[t][u][2] + b0, v11 = acc[t][u][3] + b1;
            if (kind == 0) {
                v00 *= 0.125f; v01 *= 0.125f; v10 *= 0.125f; v11 *= 0.125f;
            }
            if (kind < 2) {
                __nv_bfloat16* dh = kind ? g_kh : g_qh;
                __nv_bfloat16* dl = kind ? g_kl : g_ql;
                __nv_bfloat162 h0p = __floats2bfloat162_rn(v00, v01);
                float2 f0 = __bfloat1622float2(h0p);
                __nv_bfloat162 l0p = __floats2bfloat162_rn(v00 - f0.x, v01 - f0.y);
                __nv_bfloat162 h1p = __floats2bfloat162_rn(v10, v11);
                float2 f1 = __bfloat1622float2(h1p);
                __nv_bfloat162 l1p = __floats2bfloat162_rn(v10 - f1.x, v11 - f1.y);
                *(uint32_t*)&dh[rg * HS + col]       = *(uint32_t*)&h0p;
                *(uint32_t*)&dl[rg * HS + col]       = *(uint32_t*)&l0p;
                *(uint32_t*)&dh[(rg + 8) * HS + col] = *(uint32_t*)&h1p;
                *(uint32_t*)&dl[(rg + 8) * HS + col] = *(uint32_t*)&l1p;
            } else {
                float vs[4] = {v00, v01, v10, v11};
                int hh[4] = {col, col + 1, col, col + 1};
                int rr[4] = {rl, rl, rl + 8, rl + 8};
                #pragma unroll
                for (int e = 0; e < 4; e++) {
                    __nv_bfloat16 hi = __float2bfloat16(vs[e]);
                    __nv_bfloat16 lo =
                        __float2bfloat16(vs[e] - __bfloat162float(hi));
                    VtSh[hh[e] * 128 + rr[e]] = hi;
                    VtSl[hh[e] * 128 + rr[e]] = lo;
                }
            }
        }
    }
    __syncthreads();
    {
        int bbb = m0 >> 11, t0 = m0 & 2047;
        #pragma unroll
        for (int q = 0; q < 8; q++) {
            int idx = q * 256 + tid;          // 0..2047
            int arr = idx >> 10;
            int j = idx & 1023;
            int h = j >> 4, cc = j & 15;
            const __nv_bfloat16* src = (arr ? VtSl : VtSh) + h * 128 + cc * 8;
            __nv_bfloat16* dst = (arr ? g_vtl : g_vth)
                                 + ((size_t)(bbb * HS + h)) * TT + t0 + cc * 8;
            *(uint4*)dst = *(const uint4*)src;
        }
    }
}

// ---------------------------------------------------------------------------
// Kernel 2: causal flash attention, mma.sync bf16, preconverted operands.
// Key-split x2 + triangle pairing: CTA (bx, b): pairI = bx>>1, part p = bx&1.
// Processes tiles {pairI, 31-pairI}; for each, key tiles kt = p, p+2, ... <= qt.
// Uniform ~16.5 steps per CTA, 256 CTAs, single wave.
// smem: 2 stages x (Kh,Kl,Vth,Vtl each 64x72 bf16 = 9216B) = 73728B dynamic.
// Writes partial (O, m, l); combine kernel merges parts.
// ---------------------------------------------------------------------------
#define STG 36864

#define LOADSTAGE(st_, kt_) do {                                              \
    uint32_t sb_ = smb + (st_) * STG;                                         \
    size_t kbase_ = ((size_t)b * TT + (size_t)(kt_) * 64) * HS;               \
    size_t vbase_ = (size_t)b * (HS * TT) + (size_t)(kt_) * 64;               \
    _Pragma("unroll")                                                         \
    for (int q_ = 0; q_ < 4; q_++) {                                          \
        int idx_ = q_ * 128 + tid;                                            \
        int r_ = idx_ >> 3, c_ = idx_ & 7;                                    \
        cp16(sb_ + r_ * 144 + c_ * 16,          g_kh + kbase_ + r_ * HS + c_ * 8);  \
        cp16(sb_ + 9216 + r_ * 144 + c_ * 16,   g_kl + kbase_ + r_ * HS + c_ * 8);  \
        cp16(sb_ + 18432 + r_ * 144 + c_ * 16,  g_vth + vbase_ + (size_t)r_ * TT + c_ * 8); \
        cp16(sb_ + 27648 + r_ * 144 + c_ * 16,  g_vtl + vbase_ + (size_t)r_ * TT + c_ * 8); \
    }                                                                         \
    asm volatile("cp.async.commit_group;");                                   \
} while (0)

__global__ void __launch_bounds__(128) attn_mma_kernel()
{
    extern __shared__ __align__(16) char smd[];
    const uint32_t smb = smem_u32(smd);
    const int pairI = blockIdx.x >> 1;
    const int p = blockIdx.x & 1;
    const int b = blockIdx.y;
    const int tid  = threadIdx.x;
    const int lane = tid & 31;
    const int w    = tid >> 5;
    const int lg   = lane >> 2;
    const int lt   = lane & 3;
    const int wrow = w * 16;

    for (int tt = 0; tt < 2; tt++) {
        const int qt = tt ? (31 - pairI) : pairI;
        const int q0 = qt * 64;

        // Q fragments straight from global bf16 (pre-scaled, pre-split)
        uint32_t qh[4][4], ql[4][4];
        {
            const size_t qb = ((size_t)b * TT + q0) * HS;
            #pragma unroll
            for (int kk = 0; kk < 4; kk++) {
                int h0 = kk * 16 + 2 * lt;
                qh[kk][0] = *(const uint32_t*)&g_qh[qb + (wrow + lg) * HS + h0];
                qh[kk][1] = *(const uint32_t*)&g_qh[qb + (wrow + lg + 8) * HS + h0];
                qh[kk][2] = *(const uint32_t*)&g_qh[qb + (wrow + lg) * HS + h0 + 8];
                qh[kk][3] = *(const uint32_t*)&g_qh[qb + (wrow + lg + 8) * HS + h0 + 8];
                ql[kk][0] = *(const uint32_t*)&g_ql[qb + (wrow + lg) * HS + h0];
                ql[kk][1] = *(const uint32_t*)&g_ql[qb + (wrow + lg + 8) * HS + h0];
                ql[kk][2] = *(const uint32_t*)&g_ql[qb + (wrow + lg) * HS + h0 + 8];
                ql[kk][3] = *(const uint32_t*)&g_ql[qb + (wrow + lg + 8) * HS + h0 + 8];
            }
        }

        float O[8][4];
        #pragma unroll
        for (int j = 0; j < 8; j++)
            #pragma unroll
            for (int e = 0; e < 4; e++) O[j][e] = 0.0f;
        float m0 = -1e30f, m1 = -1e30f, l0 = 0.0f, l1 = 0.0f;

        const int nkt = (qt >= p) ? (((qt - p) >> 1) + 1) : 0;

        __syncthreads();                 // stage buffers free before reuse
        if (nkt > 0) LOADSTAGE(0, p);

        for (int i = 0; i < nkt; i++) {
            const int kt = p + 2 * i;
            const int st = i & 1;
            if (i) __syncthreads();      // compute i-1 done before buf reuse
            if (i + 1 < nkt) {
                LOADSTAGE((i + 1) & 1, kt + 2);
                asm volatile("cp.async.wait_group 1;");
            } else {
                asm volatile("cp.async.wait_group 0;");
            }
            __syncthreads();

            const __nv_bfloat16* Ksh = (const __nv_bfloat16*)(smd + st * STG);
            const __nv_bfloat16* Ksl = (const __nv_bfloat16*)(smd + st * STG + 9216);
            const __nv_bfloat16* Vsh = (const __nv_bfloat16*)(smd + st * STG + 18432);
            const __nv_bfloat16* Vsl = (const __nv_bfloat16*)(smd + st * STG + 27648);

            // ---- S = Q K^T (3-term)
            float s[8][4];
            #pragma unroll
            for (int j = 0; j < 8; j++)
                #pragma unroll
                for (int e = 0; e < 4; e++) s[j][e] = 0.0f;

            #pragma unroll
            for (int kk = 0; kk < 4; kk++) {
                int h0 = kk * 16 + 2 * lt;
                #pragma unroll
                for (int j = 0; j < 8; j++) {
                    int key = j * 8 + lg;
                    uint32_t bh[2], bl[2];
                    bh[0] = *(const uint32_t*)&Ksh[key * 72 + h0];
                    bh[1] = *(const uint32_t*)&Ksh[key * 72 + h0 + 8];
                    bl[0] = *(const uint32_t*)&Ksl[key * 72 + h0];
                    bl[1] = *(const uint32_t*)&Ksl[key * 72 + h0 + 8];
                    mma16816(s[j], qh[kk], bh);
                    mma16816(s[j], qh[kk], bl);
                    mma16816(s[j], ql[kk], bh);
                }
            }

            // ---- causal mask (diagonal tile only)
            if (kt == qt) {
                #pragma unroll
                for (int j = 0; j < 8; j++) {
                    int lc = j * 8 + 2 * lt;
                    int r0 = wrow + lg, r1 = r0 + 8;
                    if (lc > r0)     s[j][0] = -1e30f;
                    if (lc + 1 > r0) s[j][1] = -1e30f;
                    if (lc > r1)     s[j][2] = -1e30f;
                    if (lc + 1 > r1) s[j][3] = -1e30f;
                }
            }

            // ---- online softmax
            {
                float mx0 = -1e30f, mx1 = -1e30f;
                #pragma unroll
                for (int j = 0; j < 8; j++) {
                    mx0 = fmaxf(mx0, fmaxf(s[j][0], s[j][1]));
                    mx1 = fmaxf(mx1, fmaxf(s[j][2], s[j][3]));
                }
                #pragma unroll
                for (int o = 1; o <= 2; o <<= 1) {
                    mx0 = fmaxf(mx0, __shfl_xor_sync(0xffffffffu, mx0, o));
                    mx1 = fmaxf(mx1, __shfl_xor_sync(0xffffffffu, mx1, o));
                }
                float mn0 = fmaxf(m0, mx0), mn1 = fmaxf(m1, mx1);
                float al0 = __expf(m0 - mn0), al1 = __expf(m1 - mn1);
                float sum0 = 0.0f, sum1 = 0.0f;
                #pragma unroll
                for (int j = 0; j < 8; j++) {
                    s[j][0] = __expf(s[j][0] - mn0);
                    s[j][1] = __expf(s[j][1] - mn0);
                    s[j][2] = __expf(s[j][2] - mn1);
                    s[j][3] = __expf(s[j][3] - mn1);
                    sum0 += s[j][0] + s[j][1];
                    sum1 += s[j][2] + s[j][3];
                }
                #pragma unroll
                for (int o = 1; o <= 2; o <<= 1) {
                    sum0 += __shfl_xor_sync(0xffffffffu, sum0, o);
                    sum1 += __shfl_xor_sync(0xffffffffu, sum1, o);
                }
                l0 = l0 * al0 + sum0;
                l1 = l1 * al1 + sum1;
                m0 = mn0; m1 = mn1;
                #pragma unroll
                for (int j = 0; j < 8; j++) {
                    O[j][0] *= al0; O[j][1] *= al0;
                    O[j][2] *= al1; O[j][3] *= al1;
                }
            }

            // ---- pack P hi/lo
            uint32_t ph[8][2], pl[8][2];
            #pragma unroll
            for (int j = 0; j < 8; j++) {
                __nv_bfloat162 h01 = __floats2bfloat162_rn(s[j][0], s[j][1]);
                __nv_bfloat162 h23 = __floats2bfloat162_rn(s[j][2], s[j][3]);
                float2 f01 = __bfloat1622float2(h01);
                float2 f23 = __bfloat1622float2(h23);
                __nv_bfloat162 q01 =
                    __floats2bfloat162_rn(s[j][0] - f01.x, s[j][1] - f01.y);
                __nv_bfloat162 q23 =
                    __floats2bfloat162_rn(s[j][2] - f23.x, s[j][3] - f23.y);
                ph[j][0] = *(uint32_t*)&h01; ph[j][1] = *(uint32_t*)&h23;
                pl[j][0] = *(uint32_t*)&q01; pl[j][1] = *(uint32_t*)&q23;
            }

            // ---- O += P @ V (3-term), V from transposed smem
            #pragma unroll
            for (int jh = 0; jh < 8; jh++) {
                int h = jh * 8 + lg;
                #pragma unroll
                for (int kk = 0; kk < 4; kk++) {
                    uint32_t vh[2], vl[2];
                    vh[0] = *(const uint32_t*)&Vsh[h * 72 + kk * 16 + 2 * lt];
                    vh[1] = *(const uint32_t*)&Vsh[h * 72 + kk * 16 + 2 * lt + 8];
                    vl[0] = *(const uint32_t*)&Vsl[h * 72 + kk * 16 + 2 * lt];
                    vl[1] = *(const uint32_t*)&Vsl[h * 72 + kk * 16 + 2 * lt + 8];
                    uint32_t aH[4] = {ph[2 * kk][0], ph[2 * kk][1],
                                      ph[2 * kk + 1][0], ph[2 * kk + 1][1]};
                    uint32_t aL[4] = {pl[2 * kk][0], pl[2 * kk][1],
                                      pl[2 * kk + 1][0], pl[2 * kk + 1][1]};
                    mma16816(O[jh], aH, vh);
                    mma16816(O[jh], aH, vl);
                    mma16816(O[jh], aL, vh);
                }
            }
        }

        // ---- write partial (unnormalized O, m, l)
        {
            const size_t r0 = (size_t)b * TT + q0 + wrow + lg;
            float* po = g_pO + (size_t)p * PSTRIDE;
            #pragma unroll
            for (int jh = 0; jh < 8; jh++) {
                int hcol = jh * 8 + 2 * lt;
                *(float2*)&po[r0 * HS + hcol] = make_float2(O[jh][0], O[jh][1]);
                *(float2*)&po[(r0 + 8) * HS + hcol] = make_float2(O[jh][2], O[jh][3]);
            }
            if (lt == 0) {
                g_pm[p * ROWS + r0] = m0;
                g_pl[p * ROWS + r0] = l0;
                g_pm[p * ROWS + r0 + 8] = m1;
                g_pl[p * ROWS + r0 + 8] = l1;
            }
        }
    }
}

// ---------------------------------------------------------------------------
// Kernel 3: merge the two key-split partials.
// ---------------------------------------------------------------------------
__global__ __launch_bounds__(256) void combine_kernel(float* __restrict__ out)
{
    int idx = blockIdx.x * 256 + threadIdx.x;    // 262144 total
    int row = idx >> 4;
    int h4 = (idx & 15) * 4;
    float m0 = g_pm[row], m1 = g_pm[ROWS + row];
    float l0 = g_pl[row], l1 = g_pl[ROWS + row];
    float M = fmaxf(m0, m1);
    float w0 = __expf(m0 - M), w1 = __expf(m1 - M);
    float inv = 1.0f / (w0 * l0 + w1 * l1);
    float4 a = *(const float4*)&g_pO[(size_t)row * HS + h4];
    float4 c = *(const float4*)&g_pO[PSTRIDE + (size_t)row * HS + h4];
    float4 o;
    o.x = (w0 * a.x + w1 * c.x) * inv;
    o.y = (w0 * a.y + w1 * c.y) * inv;
    o.z = (w0 * a.z + w1 * c.z) * inv;
    o.w = (w0 * a.w + w1 * c.w) * inv;
    *(float4*)&out[(size_t)row * HS + h4] = o;
}

// ---------------------------------------------------------------------------
extern "C" void kernel_launch(void* const* d_in, const int* in_sizes, int n_in,
                              void* d_out, int out_size)
{
    const float* X  = (const float*)d_in[0];
    const float* Wq = (const float*)d_in[1];
    const float* bq = (const float*)d_in[2];
    const float* Wk = (const float*)d_in[3];
    const float* bk = (const float*)d_in[4];
    const float* Wv = (const float*)d_in[5];
    const float* bv = (const float*)d_in[6];
    float* out = (float*)d_out;

    static int attr_set = 0;
    if (!attr_set) {
        cudaFuncSetAttribute(qkv_mma_kernel,
                             cudaFuncAttributeMaxDynamicSharedMemorySize,
                             SMEM_QKV);
        cudaFuncSetAttribute(attn_mma_kernel,
                             cudaFuncAttributeMaxDynamicSharedMemorySize,
                             2 * STG);
        attr_set = 1;
    }

    w_convert_kernel<<<192, 256>>>(Wq, Wk, Wv);
    qkv_mma_kernel<<<128, 256, SMEM_QKV>>>(X, bq, bk, bv);

    dim3 g2(32, BB);                       // pairs x parts, batches
    attn_mma_kernel<<<g2, 128, 2 * STG>>>();

    combine_kernel<<<ROWS * HS / 4 / 256, 256>>>(out);
}

// round 6
// speedup vs baseline: 4.3067x; 1.1212x over previous
#include <cuda_runtime.h>
#include <cuda_bf16.h>
#include <cuda_fp16.h>
#include <cstdint>

#define BB 8
#define TT 2048
#define EE 1024
#define HS 64
#define NTOT 192   // q(64) | k(64) | v(64)
#define ROWS (BB * TT)
#define PSTRIDE (BB * TT * HS)

// Preconverted operands (written by qkv epilogue)
__device__ __nv_bfloat16 g_qh[ROWS * HS];   // Q hi, pre-scaled 0.125, [B*T][64]
__device__ __nv_bfloat16 g_ql[ROWS * HS];
__device__ __nv_bfloat16 g_kh[ROWS * HS];   // K hi [B*T][64]
__device__ __nv_bfloat16 g_kl[ROWS * HS];
__device__ __half        g_vth[BB * HS * TT];  // V transposed [B][64h][2048t], fp16 hi
__device__ __half        g_vtl[BB * HS * TT];  // fp16 lo
// Weights bf16 hi/lo
__device__ __nv_bfloat16 g_Wh[NTOT * EE];
__device__ __nv_bfloat16 g_Wl[NTOT * EE];
// Attention partials (2 key-split parts)
__device__ float g_pO[2 * PSTRIDE];
__device__ float g_pm[2 * ROWS];
__device__ float g_pl[2 * ROWS];

// ---------------------------------------------------------------------------
// Helpers
// ---------------------------------------------------------------------------
__device__ __forceinline__ uint32_t smem_u32(const void* p) {
    uint32_t a;
    asm("{ .reg .u64 t; cvta.to.shared.u64 t, %1; cvt.u32.u64 %0, t; }"
        : "=r"(a) : "l"(p));
    return a;
}

__device__ __forceinline__ void cp16(uint32_t dst, const void* src) {
    asm volatile("cp.async.cg.shared.global [%0], [%1], 16;"
                 :: "r"(dst), "l"(src));
}

// bf16 mma, fp32 accum
__device__ __forceinline__ void mma16816(float* c, const uint32_t* a,
                                         const uint32_t* b) {
    asm volatile(
        "mma.sync.aligned.m16n8k16.row.col.f32.bf16.bf16.f32 "
        "{%0,%1,%2,%3}, {%4,%5,%6,%7}, {%8,%9}, {%0,%1,%2,%3};"
        : "+f"(c[0]), "+f"(c[1]), "+f"(c[2]), "+f"(c[3])
        : "r"(a[0]), "r"(a[1]), "r"(a[2]), "r"(a[3]), "r"(b[0]), "r"(b[1]));
}

// fp16 mma, fp32 accum
__device__ __forceinline__ void mma16816h(float* c, const uint32_t* a,
                                          const uint32_t* b) {
    asm volatile(
        "mma.sync.aligned.m16n8k16.row.col.f32.f16.f16.f32 "
        "{%0,%1,%2,%3}, {%4,%5,%6,%7}, {%8,%9}, {%0,%1,%2,%3};"
        : "+f"(c[0]), "+f"(c[1]), "+f"(c[2]), "+f"(c[3])
        : "r"(a[0]), "r"(a[1]), "r"(a[2]), "r"(a[3]), "r"(b[0]), "r"(b[1]));
}

// ldmatrix x4 (non-trans, b16)
__device__ __forceinline__ void ldmx4(uint32_t* r, uint32_t addr) {
    asm volatile(
        "ldmatrix.sync.aligned.m8n8.x4.shared.b16 {%0,%1,%2,%3}, [%4];"
        : "=r"(r[0]), "=r"(r[1]), "=r"(r[2]), "=r"(r[3]) : "r"(addr));
}

// hi/lo bf16 split of a float4
__device__ __forceinline__ void split4(float4 v, uint2& hi, uint2& lo) {
    __nv_bfloat162 h0 = __floats2bfloat162_rn(v.x, v.y);
    __nv_bfloat162 h1 = __floats2bfloat162_rn(v.z, v.w);
    float2 f0 = __bfloat1622float2(h0);
    float2 f1 = __bfloat1622float2(h1);
    __nv_bfloat162 l0 = __floats2bfloat162_rn(v.x - f0.x, v.y - f0.y);
    __nv_bfloat162 l1 = __floats2bfloat162_rn(v.z - f1.x, v.w - f1.y);
    hi.x = *(uint32_t*)&h0; hi.y = *(uint32_t*)&h1;
    lo.x = *(uint32_t*)&l0; lo.y = *(uint32_t*)&l1;
}

// ---------------------------------------------------------------------------
// Kernel 0: convert concat(Wq,Wk,Wv) fp32 -> bf16 hi/lo
// ---------------------------------------------------------------------------
__global__ __launch_bounds__(256) void w_convert_kernel(
    const float* __restrict__ Wq, const float* __restrict__ Wk,
    const float* __restrict__ Wv)
{
    int idx = blockIdx.x * 256 + threadIdx.x;
    int e4 = idx * 4;
    int n = e4 >> 10;
    int c = e4 & 1023;
    const float* src = (n < 64) ? &Wq[n * 1024 + c]
                     : (n < 128) ? &Wk[(n - 64) * 1024 + c]
                     : &Wv[(n - 128) * 1024 + c];
    float4 v = *(const float4*)src;
    uint2 hi, lo;
    split4(v, hi, lo);
    *(uint2*)&g_Wh[e4] = hi;
    *(uint2*)&g_Wl[e4] = lo;
}

// ---------------------------------------------------------------------------
// Kernel 1: QKV projection (mma.sync bf16, 3-term).  Epilogue emits bf16
// hi/lo Q (scaled) and K, and fp16 hi/lo smem-transposed V.
// ---------------------------------------------------------------------------
#define STAGE 40960
#define BOFF  16384
#define SMEM_QKV (2 * STAGE)

__global__ void __launch_bounds__(256) qkv_mma_kernel(
    const float* __restrict__ X,
    const float* __restrict__ bq, const float* __restrict__ bk,
    const float* __restrict__ bv)
{
    extern __shared__ __align__(128) char sm[];
    const uint32_t smb = smem_u32(sm);
    const int tid = threadIdx.x;
    const int lid = tid & 31;
    const int wid = tid >> 5;
    const int wm  = wid >> 2;
    const int wn  = wid & 3;
    const int lg  = lid >> 2;
    const int lt  = lid & 3;
    const int m0  = blockIdx.x * 128;

    float acc[4][6][4];
    #pragma unroll
    for (int t = 0; t < 4; t++)
        #pragma unroll
        for (int u = 0; u < 6; u++)
            #pragma unroll
            for (int r = 0; r < 4; r++) acc[t][u][r] = 0.0f;

    float4 xr[4];

    {
        const int k0 = 0;
        #pragma unroll
        for (int p = 0; p < 4; p++) {
            int i = p * 256 + tid;
            int row = i >> 3, c4 = (i & 7) * 4;
            xr[p] = *(const float4*)&X[(size_t)(m0 + row) * EE + k0 + c4];
        }
        #pragma unroll
        for (int j = 0; j < 6; j++) {
            int idx = j * 256 + tid;
            int n = idx >> 3, u = idx & 7;
            int kg = u & 3, wh = u >> 2;
            const __nv_bfloat16* s =
                (wh ? g_Wl : g_Wh) + n * EE + k0 + kg * 8;
            cp16(smb + BOFF + n * 128 + ((u ^ (n & 7)) * 16), s);
        }
        asm volatile("cp.async.commit_group;");
        #pragma unroll
        for (int p = 0; p < 4; p++) {
            int i = p * 256 + tid;
            int row = i >> 3, c4 = (i & 7) * 4;
            int kg = c4 >> 3, bo = (c4 & 4) * 2;
            uint2 hi, lo;
            split4(xr[p], hi, lo);
            *(uint2*)(sm + row * 128 + ((kg ^ (row & 7)) * 16) + bo) = hi;
            *(uint2*)(sm + row * 128 + (((kg | 4) ^ (row & 7)) * 16) + bo) = lo;
        }
        asm volatile("cp.async.wait_group 0;");
        __syncthreads();
    }

    for (int c = 0; c < 32; c++) {
        const int cb = c & 1;
        const int nb = (c + 1) & 1;
        if (c < 31) {
            const int k0 = (c + 1) * 32;
            #pragma unroll
            for (int p = 0; p < 4; p++) {
                int i = p * 256 + tid;
                int row = i >> 3, c4 = (i & 7) * 4;
                xr[p] = *(const float4*)&X[(size_t)(m0 + row) * EE + k0 + c4];
            }
            #pragma unroll
            for (int j = 0; j < 6; j++) {
                int idx = j * 256 + tid;
                int n = idx >> 3, u = idx & 7;
                int kg = u & 3, wh = u >> 2;
                const __nv_bfloat16* s =
                    (wh ? g_Wl : g_Wh) + n * EE + k0 + kg * 8;
                cp16(smb + nb * STAGE + BOFF + n * 128 + ((u ^ (n & 7)) * 16), s);
            }
            asm volatile("cp.async.commit_group;");
        }

        const char* ab = sm + cb * STAGE;
        const char* bb = ab + BOFF;
        #pragma unroll
        for (int h = 0; h < 2; h++) {
            uint32_t afh[4][4], afl[4][4], bfh[6][2], bfl[6][2];
            #pragma unroll
            for (int t = 0; t < 4; t++) {
                int r  = wm * 64 + t * 16 + lg;
                int r8 = r + 8;
                int kg0 = 2 * h, kg1 = 2 * h + 1;
                afh[t][0] = *(const uint32_t*)(ab + r  * 128 + ((kg0 ^ (r  & 7)) * 16) + lt * 4);
                afh[t][1] = *(const uint32_t*)(ab + r8 * 128 + ((kg0 ^ (r8 & 7)) * 16) + lt * 4);
                afh[t][2] = *(const uint32_t*)(ab + r  * 128 + ((kg1 ^ (r  & 7)) * 16) + lt * 4);
                afh[t][3] = *(const uint32_t*)(ab + r8 * 128 + ((kg1 ^ (r8 & 7)) * 16) + lt * 4);
                afl[t][0] = *(const uint32_t*)(ab + r  * 128 + (((kg0 | 4) ^ (r  & 7)) * 16) + lt * 4);
                afl[t][1] = *(const uint32_t*)(ab + r8 * 128 + (((kg0 | 4) ^ (r8 & 7)) * 16) + lt * 4);
                afl[t][2] = *(const uint32_t*)(ab + r  * 128 + (((kg1 | 4) ^ (r  & 7)) * 16) + lt * 4);
                afl[t][3] = *(const uint32_t*)(ab + r8 * 128 + (((kg1 | 4) ^ (r8 & 7)) * 16) + lt * 4);
            }
            #pragma unroll
            for (int u = 0; u < 6; u++) {
                int n = wn * 48 + u * 8 + lg;
                int kg0 = 2 * h, kg1 = 2 * h + 1;
                bfh[u][0] = *(const uint32_t*)(bb + n * 128 + ((kg0 ^ (n & 7)) * 16) + lt * 4);
                bfh[u][1] = *(const uint32_t*)(bb + n * 128 + ((kg1 ^ (n & 7)) * 16) + lt * 4);
                bfl[u][0] = *(const uint32_t*)(bb + n * 128 + (((kg0 | 4) ^ (n & 7)) * 16) + lt * 4);
                bfl[u][1] = *(const uint32_t*)(bb + n * 128 + (((kg1 | 4) ^ (n & 7)) * 16) + lt * 4);
            }
            #pragma unroll
            for (int t = 0; t < 4; t++)
                #pragma unroll
                for (int u = 0; u < 6; u++)
                    mma16816(acc[t][u], afh[t], bfh[u]);
            #pragma unroll
            for (int t = 0; t < 4; t++)
                #pragma unroll
                for (int u = 0; u < 6; u++)
                    mma16816(acc[t][u], afh[t], bfl[u]);
            #pragma unroll
            for (int t = 0; t < 4; t++)
                #pragma unroll
                for (int u = 0; u < 6; u++)
                    mma16816(acc[t][u], afl[t], bfh[u]);
        }

        if (c < 31) {
            #pragma unroll
            for (int p = 0; p < 4; p++) {
                int i = p * 256 + tid;
                int row = i >> 3, c4 = (i & 7) * 4;
                int kg = c4 >> 3, bo = (c4 & 4) * 2;
                uint2 hi, lo;
                split4(xr[p], hi, lo);
                *(uint2*)(sm + nb * STAGE + row * 128 + ((kg ^ (row & 7)) * 16) + bo) = hi;
                *(uint2*)(sm + nb * STAGE + row * 128 + (((kg | 4) ^ (row & 7)) * 16) + bo) = lo;
            }
            asm volatile("cp.async.wait_group 0;");
        }
        __syncthreads();
    }

    // ---- epilogue: bias, convert; V -> fp16 hi/lo transposed via smem
    __half* VtSh = (__half*)sm;                  // [64h][128 rl]
    __half* VtSl = (__half*)(sm + 16384);

    #pragma unroll
    for (int t = 0; t < 4; t++) {
        int rl = wm * 64 + t * 16 + lg;            // local rows rl, rl+8
        size_t rg = (size_t)(m0 + rl);
        #pragma unroll
        for (int u = 0; u < 6; u++) {
            int n = wn * 48 + u * 8 + lt * 2;
            const float* barr; int col; int kind;
            if (n < 64)       { col = n;       barr = bq; kind = 0; }
            else if (n < 128) { col = n - 64;  barr = bk; kind = 1; }
            else              { col = n - 128; barr = bv; kind = 2; }
            float b0 = __ldg(&barr[col]), b1 = __ldg(&barr[col + 1]);
            float v00 = acc[t][u][0] + b0, v01 = acc[t][u][1] + b1;
            float v10 = acc[t][u][2] + b0, v11 = acc[t][u][3] + b1;
            if (kind == 0) {
                v00 *= 0.125f; v01 *= 0.125f; v10 *= 0.125f; v11 *= 0.125f;
            }
            if (kind < 2) {
                __nv_bfloat16* dh = kind ? g_kh : g_qh;
                __nv_bfloat16* dl = kind ? g_kl : g_ql;
                __nv_bfloat162 h0p = __floats2bfloat162_rn(v00, v01);
                float2 f0 = __bfloat1622float2(h0p);
                __nv_bfloat162 l0p = __floats2bfloat162_rn(v00 - f0.x, v01 - f0.y);
                __nv_bfloat162 h1p = __floats2bfloat162_rn(v10, v11);
                float2 f1 = __bfloat1622float2(h1p);
                __nv_bfloat162 l1p = __floats2bfloat162_rn(v10 - f1.x, v11 - f1.y);
                *(uint32_t*)&dh[rg * HS + col]       = *(uint32_t*)&h0p;
                *(uint32_t*)&dl[rg * HS + col]       = *(uint32_t*)&l0p;
                *(uint32_t*)&dh[(rg + 8) * HS + col] = *(uint32_t*)&h1p;
                *(uint32_t*)&dl[(rg + 8) * HS + col] = *(uint32_t*)&l1p;
            } else {
                float vs[4] = {v00, v01, v10, v11};
                int hh[4] = {col, col + 1, col, col + 1};
                int rr[4] = {rl, rl, rl + 8, rl + 8};
                #pragma unroll
                for (int e = 0; e < 4; e++) {
                    __half hi = __float2half_rn(vs[e]);
                    __half lo = __float2half_rn(vs[e] - __half2float(hi));
                    VtSh[hh[e] * 128 + rr[e]] = hi;
                    VtSl[hh[e] * 128 + rr[e]] = lo;
                }
            }
        }
    }
    __syncthreads();
    {
        int bbb = m0 >> 11, t0 = m0 & 2047;
        #pragma unroll
        for (int q = 0; q < 8; q++) {
            int idx = q * 256 + tid;          // 0..2047
            int arr = idx >> 10;
            int j = idx & 1023;
            int h = j >> 4, cc = j & 15;
            const __half* src = (arr ? VtSl : VtSh) + h * 128 + cc * 8;
            __half* dst = (arr ? g_vtl : g_vth)
                          + ((size_t)(bbb * HS + h)) * TT + t0 + cc * 8;
            *(uint4*)dst = *(const uint4*)src;
        }
    }
}

// ---------------------------------------------------------------------------
// Kernel 2: causal flash attention, mma.sync, preconverted operands.
// S = QK^T: bf16 3-term.  O = PV: fp16 2-term (P fp16, V fp16 hi/lo).
// B-fragments via ldmatrix.m8n8.x4 (non-trans layout matches row-major
// [key][h] K and [h][t] V exactly; 144B row stride -> conflict-free).
// Key-split x2 + triangle pairing (uniform ~16.5 steps), partial outputs.
// ---------------------------------------------------------------------------
#define STG 36864

#define LOADSTAGE(st_, kt_) do {                                              \
    uint32_t sb_ = smb + (st_) * STG;                                         \
    size_t kbase_ = ((size_t)b * TT + (size_t)(kt_) * 64) * HS;               \
    size_t vbase_ = (size_t)b * (HS * TT) + (size_t)(kt_) * 64;               \
    _Pragma("unroll")                                                         \
    for (int q_ = 0; q_ < 4; q_++) {                                          \
        int idx_ = q_ * 128 + tid;                                            \
        int r_ = idx_ >> 3, c_ = idx_ & 7;                                    \
        cp16(sb_ + r_ * 144 + c_ * 16,          g_kh + kbase_ + r_ * HS + c_ * 8);  \
        cp16(sb_ + 9216 + r_ * 144 + c_ * 16,   g_kl + kbase_ + r_ * HS + c_ * 8);  \
        cp16(sb_ + 18432 + r_ * 144 + c_ * 16,  g_vth + vbase_ + (size_t)r_ * TT + c_ * 8); \
        cp16(sb_ + 27648 + r_ * 144 + c_ * 16,  g_vtl + vbase_ + (size_t)r_ * TT + c_ * 8); \
    }                                                                         \
    asm volatile("cp.async.commit_group;");                                   \
} while (0)

__global__ void __launch_bounds__(128) attn_mma_kernel()
{
    extern __shared__ __align__(16) char smd[];
    const uint32_t smb = smem_u32(smd);
    const int pairI = blockIdx.x >> 1;
    const int p = blockIdx.x & 1;
    const int b = blockIdx.y;
    const int tid  = threadIdx.x;
    const int lane = tid & 31;
    const int w    = tid >> 5;
    const int lg   = lane >> 2;
    const int lt   = lane & 3;
    const int wrow = w * 16;

    // ldmatrix lane-invariant byte offset: gg = lane>>3 selects
    // (row-block, col-block) of the 4 fetched 8x8 matrices.
    const int gg = lane >> 3, ii = lane & 7;
    const uint32_t lih =
        (uint32_t)(((((gg >> 1) * 8) + ii) * 72 + (gg & 1) * 8) * 2);

    for (int tt = 0; tt < 2; tt++) {
        const int qt = tt ? (31 - pairI) : pairI;
        const int q0 = qt * 64;

        // Q fragments straight from global bf16 (pre-scaled, pre-split)
        uint32_t qh[4][4], ql[4][4];
        {
            const size_t qb = ((size_t)b * TT + q0) * HS;
            #pragma unroll
            for (int kk = 0; kk < 4; kk++) {
                int h0 = kk * 16 + 2 * lt;
                qh[kk][0] = *(const uint32_t*)&g_qh[qb + (wrow + lg) * HS + h0];
                qh[kk][1] = *(const uint32_t*)&g_qh[qb + (wrow + lg + 8) * HS + h0];
                qh[kk][2] = *(const uint32_t*)&g_qh[qb + (wrow + lg) * HS + h0 + 8];
                qh[kk][3] = *(const uint32_t*)&g_qh[qb + (wrow + lg + 8) * HS + h0 + 8];
                ql[kk][0] = *(const uint32_t*)&g_ql[qb + (wrow + lg) * HS + h0];
                ql[kk][1] = *(const uint32_t*)&g_ql[qb + (wrow + lg + 8) * HS + h0];
                ql[kk][2] = *(const uint32_t*)&g_ql[qb + (wrow + lg) * HS + h0 + 8];
                ql[kk][3] = *(const uint32_t*)&g_ql[qb + (wrow + lg + 8) * HS + h0 + 8];
            }
        }

        float O[8][4];
        #pragma unroll
        for (int j = 0; j < 8; j++)
            #pragma unroll
            for (int e = 0; e < 4; e++) O[j][e] = 0.0f;
        float m0 = -1e30f, m1 = -1e30f, l0 = 0.0f, l1 = 0.0f;

        const int nkt = (qt >= p) ? (((qt - p) >> 1) + 1) : 0;

        __syncthreads();                 // stage buffers free before reuse
        if (nkt > 0) LOADSTAGE(0, p);

        for (int i = 0; i < nkt; i++) {
            const int kt = p + 2 * i;
            const int st = i & 1;
            if (i) __syncthreads();      // compute i-1 done before buf reuse
            if (i + 1 < nkt) {
                LOADSTAGE((i + 1) & 1, kt + 2);
                asm volatile("cp.async.wait_group 1;");
            } else {
                asm volatile("cp.async.wait_group 0;");
            }
            __syncthreads();

            const uint32_t smKh = smb + st * STG;
            const uint32_t smKl = smKh + 9216;
            const uint32_t smVh = smKh + 18432;
            const uint32_t smVl = smKh + 27648;

            // ---- S = Q K^T (bf16 3-term), B-frags via ldmatrix.x4
            float s[8][4];
            #pragma unroll
            for (int j = 0; j < 8; j++)
                #pragma unroll
                for (int e = 0; e < 4; e++) s[j][e] = 0.0f;

            #pragma unroll
            for (int kk = 0; kk < 4; kk++) {
                #pragma unroll
                for (int jp = 0; jp < 4; jp++) {
                    uint32_t bh[4], bl[4];
                    ldmx4(bh, smKh + lih + jp * 2304 + kk * 32);
                    ldmx4(bl, smKl + lih + jp * 2304 + kk * 32);
                    mma16816(s[2 * jp],     qh[kk], &bh[0]);
                    mma16816(s[2 * jp],     qh[kk], &bl[0]);
                    mma16816(s[2 * jp],     ql[kk], &bh[0]);
                    mma16816(s[2 * jp + 1], qh[kk], &bh[2]);
                    mma16816(s[2 * jp + 1], qh[kk], &bl[2]);
                    mma16816(s[2 * jp + 1], ql[kk], &bh[2]);
                }
            }

            // ---- causal mask (diagonal tile only)
            if (kt == qt) {
                #pragma unroll
                for (int j = 0; j < 8; j++) {
                    int lc = j * 8 + 2 * lt;
                    int r0 = wrow + lg, r1 = r0 + 8;
                    if (lc > r0)     s[j][0] = -1e30f;
                    if (lc + 1 > r0) s[j][1] = -1e30f;
                    if (lc > r1)     s[j][2] = -1e30f;
                    if (lc + 1 > r1) s[j][3] = -1e30f;
                }
            }

            // ---- online softmax
            {
                float mx0 = -1e30f, mx1 = -1e30f;
                #pragma unroll
                for (int j = 0; j < 8; j++) {
                    mx0 = fmaxf(mx0, fmaxf(s[j][0], s[j][1]));
                    mx1 = fmaxf(mx1, fmaxf(s[j][2], s[j][3]));
                }
                #pragma unroll
                for (int o = 1; o <= 2; o <<= 1) {
                    mx0 = fmaxf(mx0, __shfl_xor_sync(0xffffffffu, mx0, o));
                    mx1 = fmaxf(mx1, __shfl_xor_sync(0xffffffffu, mx1, o));
                }
                float mn0 = fmaxf(m0, mx0), mn1 = fmaxf(m1, mx1);
                float al0 = __expf(m0 - mn0), al1 = __expf(m1 - mn1);
                float sum0 = 0.0f, sum1 = 0.0f;
                #pragma unroll
                for (int j = 0; j < 8; j++) {
                    s[j][0] = __expf(s[j][0] - mn0);
                    s[j][1] = __expf(s[j][1] - mn0);
                    s[j][2] = __expf(s[j][2] - mn1);
                    s[j][3] = __expf(s[j][3] - mn1);
                    sum0 += s[j][0] + s[j][1];
                    sum1 += s[j][2] + s[j][3];
                }
                #pragma unroll
                for (int o = 1; o <= 2; o <<= 1) {
                    sum0 += __shfl_xor_sync(0xffffffffu, sum0, o);
                    sum1 += __shfl_xor_sync(0xffffffffu, sum1, o);
                }
                l0 = l0 * al0 + sum0;
                l1 = l1 * al1 + sum1;
                m0 = mn0; m1 = mn1;
                #pragma unroll
                for (int j = 0; j < 8; j++) {
                    O[j][0] *= al0; O[j][1] *= al0;
                    O[j][2] *= al1; O[j][3] *= al1;
                }
            }

            // ---- pack P -> fp16 (single precision level)
            uint32_t pp[8][2];
            #pragma unroll
            for (int j = 0; j < 8; j++) {
                __half2 a01 = __floats2half2_rn(s[j][0], s[j][1]);
                __half2 a23 = __floats2half2_rn(s[j][2], s[j][3]);
                pp[j][0] = *(uint32_t*)&a01;
                pp[j][1] = *(uint32_t*)&a23;
            }

            // ---- O += P @ V (fp16 2-term), V-frags via ldmatrix.x4
            #pragma unroll
            for (int jhp = 0; jhp < 4; jhp++) {
                #pragma unroll
                for (int kk = 0; kk < 4; kk++) {
                    uint32_t vh[4], vl[4];
                    ldmx4(vh, smVh + lih + jhp * 2304 + kk * 32);
                    ldmx4(vl, smVl + lih + jhp * 2304 + kk * 32);
                    uint32_t aP[4] = {pp[2 * kk][0], pp[2 * kk][1],
                                      pp[2 * kk + 1][0], pp[2 * kk + 1][1]};
                    mma16816h(O[2 * jhp],     aP, &vh[0]);
                    mma16816h(O[2 * jhp],     aP, &vl[0]);
                    mma16816h(O[2 * jhp + 1], aP, &vh[2]);
                    mma16816h(O[2 * jhp + 1], aP, &vl[2]);
                }
            }
        }

        // ---- write partial (unnormalized O, m, l)
        {
            const size_t r0 = (size_t)b * TT + q0 + wrow + lg;
            float* po = g_pO + (size_t)p * PSTRIDE;
            #pragma unroll
            for (int jh = 0; jh < 8; jh++) {
                int hcol = jh * 8 + 2 * lt;
                *(float2*)&po[r0 * HS + hcol] = make_float2(O[jh][0], O[jh][1]);
                *(float2*)&po[(r0 + 8) * HS + hcol] = make_float2(O[jh][2], O[jh][3]);
            }
            if (lt == 0) {
                g_pm[p * ROWS + r0] = m0;
                g_pl[p * ROWS + r0] = l0;
                g_pm[p * ROWS + r0 + 8] = m1;
                g_pl[p * ROWS + r0 + 8] = l1;
            }
        }
    }
}

// ---------------------------------------------------------------------------
// Kernel 3: merge the two key-split partials.
// ---------------------------------------------------------------------------
__global__ __launch_bounds__(256) void combine_kernel(float* __restrict__ out)
{
    int idx = blockIdx.x * 256 + threadIdx.x;    // 262144 total
    int row = idx >> 4;
    int h4 = (idx & 15) * 4;
    float m0 = g_pm[row], m1 = g_pm[ROWS + row];
    float l0 = g_pl[row], l1 = g_pl[ROWS + row];
    float M = fmaxf(m0, m1);
    float w0 = __expf(m0 - M), w1 = __expf(m1 - M);
    float inv = 1.0f / (w0 * l0 + w1 * l1);
    float4 a = *(const float4*)&g_pO[(size_t)row * HS + h4];
    float4 c = *(const float4*)&g_pO[PSTRIDE + (size_t)row * HS + h4];
    float4 o;
    o.x = (w0 * a.x + w1 * c.x) * inv;
    o.y = (w0 * a.y + w1 * c.y) * inv;
    o.z = (w0 * a.z + w1 * c.z) * inv;
    o.w = (w0 * a.w + w1 * c.w) * inv;
    *(float4*)&out[(size_t)row * HS + h4] = o;
}

// ---------------------------------------------------------------------------
extern "C" void kernel_launch(void* const* d_in, const int* in_sizes, int n_in,
                              void* d_out, int out_size)
{
    const float* X  = (const float*)d_in[0];
    const float* Wq = (const float*)d_in[1];
    const float* bq = (const float*)d_in[2];
    const float* Wk = (const float*)d_in[3];
    const float* bk = (const float*)d_in[4];
    const float* Wv = (const float*)d_in[5];
    const float* bv = (const float*)d_in[6];
    float* out = (float*)d_out;

    static int attr_set = 0;
    if (!attr_set) {
        cudaFuncSetAttribute(qkv_mma_kernel,
                             cudaFuncAttributeMaxDynamicSharedMemorySize,
                             SMEM_QKV);
        cudaFuncSetAttribute(attn_mma_kernel,
                             cudaFuncAttributeMaxDynamicSharedMemorySize,
                             2 * STG);
        attr_set = 1;
    }

    w_convert_kernel<<<192, 256>>>(Wq, Wk, Wv);
    qkv_mma_kernel<<<128, 256, SMEM_QKV>>>(X, bq, bk, bv);

    dim3 g2(32, BB);                       // pairs x parts, batches
    attn_mma_kernel<<<g2, 128, 2 * STG>>>();

    combine_kernel<<<ROWS * HS / 4 / 256, 256>>>(out);
}

// round 7
// speedup vs baseline: 5.2911x; 1.2286x over previous
#include <cuda_runtime.h>
#include <cuda_bf16.h>
#include <cuda_fp16.h>
#include <cstdint>

#define BB 8
#define TT 2048
#define EE 1024
#define HS 64
#define NTOT 192   // q(64) | k(64) | v(64)
#define ROWS (BB * TT)
#define PSTRIDE (BB * TT * HS)

// Preconverted operands (written by qkv epilogue)
__device__ __nv_bfloat16 g_qh[ROWS * HS];   // Q hi, pre-scaled 0.125, [B*T][64]
__device__ __nv_bfloat16 g_ql[ROWS * HS];
__device__ __nv_bfloat16 g_kh[ROWS * HS];   // K hi [B*T][64]
__device__ __nv_bfloat16 g_kl[ROWS * HS];
__device__ __half        g_vth[BB * HS * TT];  // V transposed [B][64h][2048t], fp16
// Weights fp16 hi/lo of (32*W)
__device__ __half g_Wh[NTOT * EE];
__device__ __half g_Wl[NTOT * EE];
// Attention partials (2 key-split parts)
__device__ float g_pO[2 * PSTRIDE];
__device__ float g_pm[2 * ROWS];
__device__ float g_pl[2 * ROWS];

// ---------------------------------------------------------------------------
// Helpers
// ---------------------------------------------------------------------------
__device__ __forceinline__ uint32_t smem_u32(const void* p) {
    uint32_t a;
    asm("{ .reg .u64 t; cvta.to.shared.u64 t, %1; cvt.u32.u64 %0, t; }"
        : "=r"(a) : "l"(p));
    return a;
}

__device__ __forceinline__ void cp16(uint32_t dst, const void* src) {
    asm volatile("cp.async.cg.shared.global [%0], [%1], 16;"
                 :: "r"(dst), "l"(src));
}

// bf16 mma, fp32 accum
__device__ __forceinline__ void mma16816(float* c, const uint32_t* a,
                                         const uint32_t* b) {
    asm volatile(
        "mma.sync.aligned.m16n8k16.row.col.f32.bf16.bf16.f32 "
        "{%0,%1,%2,%3}, {%4,%5,%6,%7}, {%8,%9}, {%0,%1,%2,%3};"
        : "+f"(c[0]), "+f"(c[1]), "+f"(c[2]), "+f"(c[3])
        : "r"(a[0]), "r"(a[1]), "r"(a[2]), "r"(a[3]), "r"(b[0]), "r"(b[1]));
}

// fp16 mma, fp32 accum
__device__ __forceinline__ void mma16816h(float* c, const uint32_t* a,
                                          const uint32_t* b) {
    asm volatile(
        "mma.sync.aligned.m16n8k16.row.col.f32.f16.f16.f32 "
        "{%0,%1,%2,%3}, {%4,%5,%6,%7}, {%8,%9}, {%0,%1,%2,%3};"
        : "+f"(c[0]), "+f"(c[1]), "+f"(c[2]), "+f"(c[3])
        : "r"(a[0]), "r"(a[1]), "r"(a[2]), "r"(a[3]), "r"(b[0]), "r"(b[1]));
}

// ldmatrix x4 (non-trans, b16)
__device__ __forceinline__ void ldmx4(uint32_t* r, uint32_t addr) {
    asm volatile(
        "ldmatrix.sync.aligned.m8n8.x4.shared.b16 {%0,%1,%2,%3}, [%4];"
        : "=r"(r[0]), "=r"(r[1]), "=r"(r[2]), "=r"(r[3]) : "r"(addr));
}

// ---------------------------------------------------------------------------
// Kernel 0: convert concat(Wq,Wk,Wv)*32 fp32 -> fp16 hi/lo, [192][1024]
// ---------------------------------------------------------------------------
__global__ __launch_bounds__(256) void w_convert_kernel(
    const float* __restrict__ Wq, const float* __restrict__ Wk,
    const float* __restrict__ Wv)
{
    int idx = blockIdx.x * 256 + threadIdx.x;
    int e4 = idx * 4;
    int n = e4 >> 10;
    int c = e4 & 1023;
    const float* src = (n < 64) ? &Wq[n * 1024 + c]
                     : (n < 128) ? &Wk[(n - 64) * 1024 + c]
                     : &Wv[(n - 128) * 1024 + c];
    float4 v = *(const float4*)src;
    float vs[4] = {v.x * 32.0f, v.y * 32.0f, v.z * 32.0f, v.w * 32.0f};
    __half h[4], l[4];
    #pragma unroll
    for (int e = 0; e < 4; e++) {
        h[e] = __float2half_rn(vs[e]);
        l[e] = __float2half_rn(vs[e] - __half2float(h[e]));
    }
    *(uint2*)&g_Wh[e4] = *(uint2*)h;
    *(uint2*)&g_Wl[e4] = *(uint2*)l;
}

// ---------------------------------------------------------------------------
// Kernel 1: QKV projection, fp16 2-term mma: X_fp16 * (32W)_hi + X * (32W)_lo.
// D[128,192] per CTA.  8 warps: 2 (M) x 4 (N).  Epilogue scales acc by 1/32.
// A stage: 128 rows x 32 fp16, 80B row stride (conflict-free a-frags).
// B stage: 192 rows x 128B (hi units 0-3, lo 4-7, XOR-swizzled by n&7).
// ---------------------------------------------------------------------------
#define ASTRIDE 80
#define BOFF  10240
#define STAGE 34816
#define SMEM_QKV (2 * STAGE)

__global__ void __launch_bounds__(256) qkv_mma_kernel(
    const float* __restrict__ X,
    const float* __restrict__ bq, const float* __restrict__ bk,
    const float* __restrict__ bv)
{
    extern __shared__ __align__(128) char sm[];
    const uint32_t smb = smem_u32(sm);
    const int tid = threadIdx.x;
    const int lid = tid & 31;
    const int wid = tid >> 5;
    const int wm  = wid >> 2;
    const int wn  = wid & 3;
    const int lg  = lid >> 2;
    const int lt  = lid & 3;
    const int m0  = blockIdx.x * 128;
    const int arow = tid >> 1;          // A-fill: row 0..127
    const int akh  = tid & 1;           // A-fill: k-half (16 floats)

    float acc[4][6][4];
    #pragma unroll
    for (int t = 0; t < 4; t++)
        #pragma unroll
        for (int u = 0; u < 6; u++)
            #pragma unroll
            for (int r = 0; r < 4; r++) acc[t][u][r] = 0.0f;

    float4 xr[4];

    // ---- prologue: chunk 0
    {
        const float* xp = &X[(size_t)(m0 + arow) * EE + akh * 16];
        #pragma unroll
        for (int p = 0; p < 4; p++) xr[p] = *(const float4*)&xp[p * 4];
        #pragma unroll
        for (int j = 0; j < 6; j++) {
            int idx = j * 256 + tid;
            int n = idx >> 3, u = idx & 7;
            int kg = u & 3, wh = u >> 2;
            const __half* s = (wh ? g_Wl : g_Wh) + n * EE + kg * 8;
            cp16(smb + BOFF + n * 128 + ((u ^ (n & 7)) * 16), s);
        }
        asm volatile("cp.async.commit_group;");
        {
            __half2 hh[8];
            #pragma unroll
            for (int p = 0; p < 4; p++) {
                hh[2 * p]     = __floats2half2_rn(xr[p].x, xr[p].y);
                hh[2 * p + 1] = __floats2half2_rn(xr[p].z, xr[p].w);
            }
            *(uint4*)(sm + arow * ASTRIDE + akh * 32)      = *(uint4*)&hh[0];
            *(uint4*)(sm + arow * ASTRIDE + akh * 32 + 16) = *(uint4*)&hh[4];
        }
        asm volatile("cp.async.wait_group 0;");
        __syncthreads();
    }

    for (int c = 0; c < 32; c++) {
        const int cb = c & 1;
        const int nb = (c + 1) & 1;
        if (c < 31) {
            const int k0 = (c + 1) * 32;
            const float* xp = &X[(size_t)(m0 + arow) * EE + k0 + akh * 16];
            #pragma unroll
            for (int p = 0; p < 4; p++) xr[p] = *(const float4*)&xp[p * 4];
            #pragma unroll
            for (int j = 0; j < 6; j++) {
                int idx = j * 256 + tid;
                int n = idx >> 3, u = idx & 7;
                int kg = u & 3, wh = u >> 2;
                const __half* s = (wh ? g_Wl : g_Wh) + n * EE + k0 + kg * 8;
                cp16(smb + nb * STAGE + BOFF + n * 128 + ((u ^ (n & 7)) * 16), s);
            }
            asm volatile("cp.async.commit_group;");
        }

        // ---- compute chunk c (two k16 steps)
        const char* ab = sm + cb * STAGE;
        const char* bb = ab + BOFF;
        #pragma unroll
        for (int h = 0; h < 2; h++) {
            uint32_t af[4][4], bfh[6][2], bfl[6][2];
            #pragma unroll
            for (int t = 0; t < 4; t++) {
                int r  = wm * 64 + t * 16 + lg;
                int r8 = r + 8;
                af[t][0] = *(const uint32_t*)(ab + r  * ASTRIDE + (2 * h) * 16 + lt * 4);
                af[t][1] = *(const uint32_t*)(ab + r8 * ASTRIDE + (2 * h) * 16 + lt * 4);
                af[t][2] = *(const uint32_t*)(ab + r  * ASTRIDE + (2 * h + 1) * 16 + lt * 4);
                af[t][3] = *(const uint32_t*)(ab + r8 * ASTRIDE + (2 * h + 1) * 16 + lt * 4);
            }
            #pragma unroll
            for (int u = 0; u < 6; u++) {
                int n = wn * 48 + u * 8 + lg;
                int kg0 = 2 * h, kg1 = 2 * h + 1;
                bfh[u][0] = *(const uint32_t*)(bb + n * 128 + ((kg0 ^ (n & 7)) * 16) + lt * 4);
                bfh[u][1] = *(const uint32_t*)(bb + n * 128 + ((kg1 ^ (n & 7)) * 16) + lt * 4);
                bfl[u][0] = *(const uint32_t*)(bb + n * 128 + (((kg0 | 4) ^ (n & 7)) * 16) + lt * 4);
                bfl[u][1] = *(const uint32_t*)(bb + n * 128 + (((kg1 | 4) ^ (n & 7)) * 16) + lt * 4);
            }
            #pragma unroll
            for (int t = 0; t < 4; t++)
                #pragma unroll
                for (int u = 0; u < 6; u++)
                    mma16816h(acc[t][u], af[t], bfh[u]);
            #pragma unroll
            for (int t = 0; t < 4; t++)
                #pragma unroll
                for (int u = 0; u < 6; u++)
                    mma16816h(acc[t][u], af[t], bfl[u]);
        }

        if (c < 31) {
            __half2 hh[8];
            #pragma unroll
            for (int p = 0; p < 4; p++) {
                hh[2 * p]     = __floats2half2_rn(xr[p].x, xr[p].y);
                hh[2 * p + 1] = __floats2half2_rn(xr[p].z, xr[p].w);
            }
            *(uint4*)(sm + nb * STAGE + arow * ASTRIDE + akh * 32)      = *(uint4*)&hh[0];
            *(uint4*)(sm + nb * STAGE + arow * ASTRIDE + akh * 32 + 16) = *(uint4*)&hh[4];
            asm volatile("cp.async.wait_group 0;");
        }
        __syncthreads();
    }

    // ---- epilogue: acc/32 + bias; Q/K -> bf16 hi/lo; V -> fp16 via smem T
    __half* VtSh = (__half*)sm;                  // [64h][128 rl]

    #pragma unroll
    for (int t = 0; t < 4; t++) {
        int rl = wm * 64 + t * 16 + lg;            // local rows rl, rl+8
        size_t rg = (size_t)(m0 + rl);
        #pragma unroll
        for (int u = 0; u < 6; u++) {
            int n = wn * 48 + u * 8 + lt * 2;
            const float* barr; int col; int kind;
            if (n < 64)       { col = n;       barr = bq; kind = 0; }
            else if (n < 128) { col = n - 64;  barr = bk; kind = 1; }
            else              { col = n - 128; barr = bv; kind = 2; }
            float b0 = __ldg(&barr[col]), b1 = __ldg(&barr[col + 1]);
            float v00 = acc[t][u][0] * 0.03125f + b0;
            float v01 = acc[t][u][1] * 0.03125f + b1;
            float v10 = acc[t][u][2] * 0.03125f + b0;
            float v11 = acc[t][u][3] * 0.03125f + b1;
            if (kind == 0) {
                v00 *= 0.125f; v01 *= 0.125f; v10 *= 0.125f; v11 *= 0.125f;
            }
            if (kind < 2) {
                __nv_bfloat16* dh = kind ? g_kh : g_qh;
                __nv_bfloat16* dl = kind ? g_kl : g_ql;
                __nv_bfloat162 h0p = __floats2bfloat162_rn(v00, v01);
                float2 f0 = __bfloat1622float2(h0p);
                __nv_bfloat162 l0p = __floats2bfloat162_rn(v00 - f0.x, v01 - f0.y);
                __nv_bfloat162 h1p = __floats2bfloat162_rn(v10, v11);
                float2 f1 = __bfloat1622float2(h1p);
                __nv_bfloat162 l1p = __floats2bfloat162_rn(v10 - f1.x, v11 - f1.y);
                *(uint32_t*)&dh[rg * HS + col]       = *(uint32_t*)&h0p;
                *(uint32_t*)&dl[rg * HS + col]       = *(uint32_t*)&l0p;
                *(uint32_t*)&dh[(rg + 8) * HS + col] = *(uint32_t*)&h1p;
                *(uint32_t*)&dl[(rg + 8) * HS + col] = *(uint32_t*)&l1p;
            } else {
                VtSh[col * 128 + rl]           = __float2half_rn(v00);
                VtSh[(col + 1) * 128 + rl]     = __float2half_rn(v01);
                VtSh[col * 128 + rl + 8]       = __float2half_rn(v10);
                VtSh[(col + 1) * 128 + rl + 8] = __float2half_rn(v11);
            }
        }
    }
    __syncthreads();
    {
        int bbb = m0 >> 11, t0 = m0 & 2047;
        #pragma unroll
        for (int q = 0; q < 4; q++) {
            int idx = q * 256 + tid;          // 0..1023
            int h = idx >> 4, cc = idx & 15;
            __half* dst = g_vth + ((size_t)(bbb * HS + h)) * TT + t0 + cc * 8;
            *(uint4*)dst = *(const uint4*)(VtSh + h * 128 + cc * 8);
        }
    }
}

// ---------------------------------------------------------------------------
// Kernel 2: causal flash attention, mma.sync, preconverted operands.
// S = QK^T: bf16 3-term.  O = PV: fp16 single-term (P fp16, V fp16).
// B-fragments via ldmatrix.m8n8.x4 (row stride 144B -> conflict-free).
// Key-split x2 + triangle pairing (uniform ~16.5 steps), partial outputs.
// ---------------------------------------------------------------------------
#define STG 27648

#define LOADSTAGE(st_, kt_) do {                                              \
    uint32_t sb_ = smb + (st_) * STG;                                         \
    size_t kbase_ = ((size_t)b * TT + (size_t)(kt_) * 64) * HS;               \
    size_t vbase_ = (size_t)b * (HS * TT) + (size_t)(kt_) * 64;               \
    _Pragma("unroll")                                                         \
    for (int q_ = 0; q_ < 4; q_++) {                                          \
        int idx_ = q_ * 128 + tid;                                            \
        int r_ = idx_ >> 3, c_ = idx_ & 7;                                    \
        cp16(sb_ + r_ * 144 + c_ * 16,          g_kh + kbase_ + r_ * HS + c_ * 8);  \
        cp16(sb_ + 9216 + r_ * 144 + c_ * 16,   g_kl + kbase_ + r_ * HS + c_ * 8);  \
        cp16(sb_ + 18432 + r_ * 144 + c_ * 16,  g_vth + vbase_ + (size_t)r_ * TT + c_ * 8); \
    }                                                                         \
    asm volatile("cp.async.commit_group;");                                   \
} while (0)

__global__ void __launch_bounds__(128) attn_mma_kernel()
{
    extern __shared__ __align__(16) char smd[];
    const uint32_t smb = smem_u32(smd);
    const int pairI = blockIdx.x >> 1;
    const int p = blockIdx.x & 1;
    const int b = blockIdx.y;
    const int tid  = threadIdx.x;
    const int lane = tid & 31;
    const int w    = tid >> 5;
    const int lg   = lane >> 2;
    const int lt   = lane & 3;
    const int wrow = w * 16;

    const int gg = lane >> 3, ii = lane & 7;
    const uint32_t lih =
        (uint32_t)(((((gg >> 1) * 8) + ii) * 72 + (gg & 1) * 8) * 2);

    for (int tt = 0; tt < 2; tt++) {
        const int qt = tt ? (31 - pairI) : pairI;
        const int q0 = qt * 64;

        // Q fragments straight from global bf16 (pre-scaled, pre-split)
        uint32_t qh[4][4], ql[4][4];
        {
            const size_t qb = ((size_t)b * TT + q0) * HS;
            #pragma unroll
            for (int kk = 0; kk < 4; kk++) {
                int h0 = kk * 16 + 2 * lt;
                qh[kk][0] = *(const uint32_t*)&g_qh[qb + (wrow + lg) * HS + h0];
                qh[kk][1] = *(const uint32_t*)&g_qh[qb + (wrow + lg + 8) * HS + h0];
                qh[kk][2] = *(const uint32_t*)&g_qh[qb + (wrow + lg) * HS + h0 + 8];
                qh[kk][3] = *(const uint32_t*)&g_qh[qb + (wrow + lg + 8) * HS + h0 + 8];
                ql[kk][0] = *(const uint32_t*)&g_ql[qb + (wrow + lg) * HS + h0];
                ql[kk][1] = *(const uint32_t*)&g_ql[qb + (wrow + lg + 8) * HS + h0];
                ql[kk][2] = *(const uint32_t*)&g_ql[qb + (wrow + lg) * HS + h0 + 8];
                ql[kk][3] = *(const uint32_t*)&g_ql[qb + (wrow + lg + 8) * HS + h0 + 8];
            }
        }

        float O[8][4];
        #pragma unroll
        for (int j = 0; j < 8; j++)
            #pragma unroll
            for (int e = 0; e < 4; e++) O[j][e] = 0.0f;
        float m0 = -1e30f, m1 = -1e30f, l0 = 0.0f, l1 = 0.0f;

        const int nkt = (qt >= p) ? (((qt - p) >> 1) + 1) : 0;

        __syncthreads();                 // stage buffers free before reuse
        if (nkt > 0) LOADSTAGE(0, p);

        for (int i = 0; i < nkt; i++) {
            const int kt = p + 2 * i;
            const int st = i & 1;
            if (i) __syncthreads();      // compute i-1 done before buf reuse
            if (i + 1 < nkt) {
                LOADSTAGE((i + 1) & 1, kt + 2);
                asm volatile("cp.async.wait_group 1;");
            } else {
                asm volatile("cp.async.wait_group 0;");
            }
            __syncthreads();

            const uint32_t smKh = smb + st * STG;
            const uint32_t smKl = smKh + 9216;
            const uint32_t smVh = smKh + 18432;

            // ---- S = Q K^T (bf16 3-term), B-frags via ldmatrix.x4
            float s[8][4];
            #pragma unroll
            for (int j = 0; j < 8; j++)
                #pragma unroll
                for (int e = 0; e < 4; e++) s[j][e] = 0.0f;

            #pragma unroll
            for (int kk = 0; kk < 4; kk++) {
                #pragma unroll
                for (int jp = 0; jp < 4; jp++) {
                    uint32_t bh[4], bl[4];
                    ldmx4(bh, smKh + lih + jp * 2304 + kk * 32);
                    ldmx4(bl, smKl + lih + jp * 2304 + kk * 32);
                    mma16816(s[2 * jp],     qh[kk], &bh[0]);
                    mma16816(s[2 * jp],     qh[kk], &bl[0]);
                    mma16816(s[2 * jp],     ql[kk], &bh[0]);
                    mma16816(s[2 * jp + 1], qh[kk], &bh[2]);
                    mma16816(s[2 * jp + 1], qh[kk], &bl[2]);
                    mma16816(s[2 * jp + 1], ql[kk], &bh[2]);
                }
            }

            // ---- causal mask (diagonal tile only)
            if (kt == qt) {
                #pragma unroll
                for (int j = 0; j < 8; j++) {
                    int lc = j * 8 + 2 * lt;
                    int r0 = wrow + lg, r1 = r0 + 8;
                    if (lc > r0)     s[j][0] = -1e30f;
                    if (lc + 1 > r0) s[j][1] = -1e30f;
                    if (lc > r1)     s[j][2] = -1e30f;
                    if (lc + 1 > r1) s[j][3] = -1e30f;
                }
            }

            // ---- online softmax
            {
                float mx0 = -1e30f, mx1 = -1e30f;
                #pragma unroll
                for (int j = 0; j < 8; j++) {
                    mx0 = fmaxf(mx0, fmaxf(s[j][0], s[j][1]));
                    mx1 = fmaxf(mx1, fmaxf(s[j][2], s[j][3]));
                }
                #pragma unroll
                for (int o = 1; o <= 2; o <<= 1) {
                    mx0 = fmaxf(mx0, __shfl_xor_sync(0xffffffffu, mx0, o));
                    mx1 = fmaxf(mx1, __shfl_xor_sync(0xffffffffu, mx1, o));
                }
                float mn0 = fmaxf(m0, mx0), mn1 = fmaxf(m1, mx1);
                float al0 = __expf(m0 - mn0), al1 = __expf(m1 - mn1);
                float sum0 = 0.0f, sum1 = 0.0f;
                #pragma unroll
                for (int j = 0; j < 8; j++) {
                    s[j][0] = __expf(s[j][0] - mn0);
                    s[j][1] = __expf(s[j][1] - mn0);
                    s[j][2] = __expf(s[j][2] - mn1);
                    s[j][3] = __expf(s[j][3] - mn1);
                    sum0 += s[j][0] + s[j][1];
                    sum1 += s[j][2] + s[j][3];
                }
                #pragma unroll
                for (int o = 1; o <= 2; o <<= 1) {
                    sum0 += __shfl_xor_sync(0xffffffffu, sum0, o);
                    sum1 += __shfl_xor_sync(0xffffffffu, sum1, o);
                }
                l0 = l0 * al0 + sum0;
                l1 = l1 * al1 + sum1;
                m0 = mn0; m1 = mn1;
                #pragma unroll
                for (int j = 0; j < 8; j++) {
                    O[j][0] *= al0; O[j][1] *= al0;
                    O[j][2] *= al1; O[j][3] *= al1;
                }
            }

            // ---- pack P -> fp16
            uint32_t pp[8][2];
            #pragma unroll
            for (int j = 0; j < 8; j++) {
                __half2 a01 = __floats2half2_rn(s[j][0], s[j][1]);
                __half2 a23 = __floats2half2_rn(s[j][2], s[j][3]);
                pp[j][0] = *(uint32_t*)&a01;
                pp[j][1] = *(uint32_t*)&a23;
            }

            // ---- O += P @ V (fp16 single-term), V-frags via ldmatrix.x4
            #pragma unroll
            for (int jhp = 0; jhp < 4; jhp++) {
                #pragma unroll
                for (int kk = 0; kk < 4; kk++) {
                    uint32_t vh[4];
                    ldmx4(vh, smVh + lih + jhp * 2304 + kk * 32);
                    uint32_t aP[4] = {pp[2 * kk][0], pp[2 * kk][1],
                                      pp[2 * kk + 1][0], pp[2 * kk + 1][1]};
                    mma16816h(O[2 * jhp],     aP, &vh[0]);
                    mma16816h(O[2 * jhp + 1], aP, &vh[2]);
                }
            }
        }

        // ---- write partial (unnormalized O, m, l)
        {
            const size_t r0 = (size_t)b * TT + q0 + wrow + lg;
            float* po = g_pO + (size_t)p * PSTRIDE;
            #pragma unroll
            for (int jh = 0; jh < 8; jh++) {
                int hcol = jh * 8 + 2 * lt;
                *(float2*)&po[r0 * HS + hcol] = make_float2(O[jh][0], O[jh][1]);
                *(float2*)&po[(r0 + 8) * HS + hcol] = make_float2(O[jh][2], O[jh][3]);
            }
            if (lt == 0) {
                g_pm[p * ROWS + r0] = m0;
                g_pl[p * ROWS + r0] = l0;
                g_pm[p * ROWS + r0 + 8] = m1;
                g_pl[p * ROWS + r0 + 8] = l1;
            }
        }
    }
}

// ---------------------------------------------------------------------------
// Kernel 3: merge the two key-split partials.
// ---------------------------------------------------------------------------
__global__ __launch_bounds__(256) void combine_kernel(float* __restrict__ out)
{
    int idx = blockIdx.x * 256 + threadIdx.x;    // 262144 total
    int row = idx >> 4;
    int h4 = (idx & 15) * 4;
    float m0 = g_pm[row], m1 = g_pm[ROWS + row];
    float l0 = g_pl[row], l1 = g_pl[ROWS + row];
    float M = fmaxf(m0, m1);
    float w0 = __expf(m0 - M), w1 = __expf(m1 - M);
    float inv = 1.0f / (w0 * l0 + w1 * l1);
    float4 a = *(const float4*)&g_pO[(size_t)row * HS + h4];
    float4 c = *(const float4*)&g_pO[PSTRIDE + (size_t)row * HS + h4];
    float4 o;
    o.x = (w0 * a.x + w1 * c.x) * inv;
    o.y = (w0 * a.y + w1 * c.y) * inv;
    o.z = (w0 * a.z + w1 * c.z) * inv;
    o.w = (w0 * a.w + w1 * c.w) * inv;
    *(float4*)&out[(size_t)row * HS + h4] = o;
}

// ---------------------------------------------------------------------------
extern "C" void kernel_launch(void* const* d_in, const int* in_sizes, int n_in,
                              void* d_out, int out_size)
{
    const float* X  = (const float*)d_in[0];
    const float* Wq = (const float*)d_in[1];
    const float* bq = (const float*)d_in[2];
    const float* Wk = (const float*)d_in[3];
    const float* bk = (const float*)d_in[4];
    const float* Wv = (const float*)d_in[5];
    const float* bv = (const float*)d_in[6];
    float* out = (float*)d_out;

    static int attr_set = 0;
    if (!attr_set) {
        cudaFuncSetAttribute(qkv_mma_kernel,
                             cudaFuncAttributeMaxDynamicSharedMemorySize,
                             SMEM_QKV);
        cudaFuncSetAttribute(attn_mma_kernel,
                             cudaFuncAttributeMaxDynamicSharedMemorySize,
                             2 * STG);
        attr_set = 1;
    }

    w_convert_kernel<<<192, 256>>>(Wq, Wk, Wv);
    qkv_mma_kernel<<<128, 256, SMEM_QKV>>>(X, bq, bk, bv);

    dim3 g2(32, BB);                       // pairs x parts, batches
    attn_mma_kernel<<<g2, 128, 2 * STG>>>();

    combine_kernel<<<ROWS * HS / 4 / 256, 256>>>(out);
}